// round 1
// baseline (speedup 1.0000x reference)
#include <cuda_runtime.h>

#define NN 20000
#define DD 64
#define KK 32

// scratch for h (output of attention+LN1), read by the GCN kernel
__device__ float g_h[NN * DD];

__global__ __launch_bounds__(64, 8)
void attn_kernel(const float* __restrict__ coords,
                 const float* __restrict__ feats,
                 const float* __restrict__ Wq, const float* __restrict__ bq,
                 const float* __restrict__ Wk, const float* __restrict__ bk,
                 const float* __restrict__ Wv, const float* __restrict__ bv,
                 const float* __restrict__ Wl1, const float* __restrict__ bl1,
                 const float* __restrict__ Wl2, const float* __restrict__ bl2,
                 const float* __restrict__ Ww1, const float* __restrict__ bw1,
                 const float* __restrict__ Ww2, const float* __restrict__ bw2,
                 const float* __restrict__ g_att, const float* __restrict__ b_att,
                 const int* __restrict__ knn)
{
    const int i = blockIdx.x;
    const int d = threadIdx.x;

    __shared__ float sF[64];           // feats[i]
    __shared__ float sC0[3];           // coords[i]
    __shared__ int   sIdx[32];         // knn[i, 0:32]
    __shared__ float sCoord[32][3];    // coords of neighbors
    __shared__ float bufA[64][8];      // ping: hid / rel   (layout [h][kk] for float4 bcast)
    __shared__ float bufB[64][8];      // pong: pe  / wh
    __shared__ float sV[32][64];       // V[k][d]
    __shared__ float sW[32][64];       // w_pre[k][d]
    __shared__ float red[4];

    sF[d] = feats[i * 64 + d];
    if (d < 32) sIdx[d] = knn[i * 33 + d];
    if (d < 3)  sC0[d]  = coords[i * 3 + d];
    __syncthreads();

    for (int t = d; t < 96; t += 64)
        sCoord[t / 3][t % 3] = coords[sIdx[t / 3] * 3 + (t % 3)];

    // Q[d] = relu(feats[i] @ Wq + bq)[d]   (kept in register; rel only needs Q[d])
    float q = bq[d];
    #pragma unroll
    for (int j = 0; j < 64; j++) q = fmaf(sF[j], Wq[j * 64 + d], q);
    q = fmaxf(q, 0.f);
    __syncthreads();   // covers sCoord

    for (int k0 = 0; k0 < 32; k0 += 8) {
        // ---- hid[kk][d] = relu(diff @ Wl1 + bl1) ----
        {
            const float b0 = bl1[d];
            const float w0 = Wl1[d], w1 = Wl1[64 + d], w2 = Wl1[128 + d];
            #pragma unroll
            for (int kk = 0; kk < 8; kk++) {
                const float dx = sCoord[k0 + kk][0] - sC0[0];
                const float dy = sCoord[k0 + kk][1] - sC0[1];
                const float dz = sCoord[k0 + kk][2] - sC0[2];
                float h = fmaf(dx, w0, fmaf(dy, w1, fmaf(dz, w2, b0)));
                bufA[d][kk] = fmaxf(h, 0.f);
            }
        }
        __syncthreads();

        // ---- fc = hid @ Wl2 + bl2 ;  pe = fc + feats[j] ----
        float fcr[8];
        {
            float acc[8];
            const float bb = bl2[d];
            #pragma unroll
            for (int kk = 0; kk < 8; kk++) acc[kk] = bb;
            #pragma unroll
            for (int h = 0; h < 64; h++) {
                const float w = Wl2[h * 64 + d];
                const float4 h0 = *(const float4*)(&bufA[h][0]);
                const float4 h1 = *(const float4*)(&bufA[h][4]);
                acc[0] = fmaf(h0.x, w, acc[0]); acc[1] = fmaf(h0.y, w, acc[1]);
                acc[2] = fmaf(h0.z, w, acc[2]); acc[3] = fmaf(h0.w, w, acc[3]);
                acc[4] = fmaf(h1.x, w, acc[4]); acc[5] = fmaf(h1.y, w, acc[5]);
                acc[6] = fmaf(h1.z, w, acc[6]); acc[7] = fmaf(h1.w, w, acc[7]);
            }
            #pragma unroll
            for (int kk = 0; kk < 8; kk++) {
                fcr[kk] = acc[kk];
                bufB[d][kk] = acc[kk] + feats[sIdx[k0 + kk] * 64 + d];
            }
        }
        __syncthreads();

        // ---- Kf = relu(pe @ Wk + bk), V = pe @ Wv + bv, rel = (Kf - Q)*fc ----
        {
            float ak[8], av[8];
            const float bkd = bk[d], bvd = bv[d];
            #pragma unroll
            for (int kk = 0; kk < 8; kk++) { ak[kk] = bkd; av[kk] = bvd; }
            #pragma unroll
            for (int h = 0; h < 64; h++) {
                const float wk = Wk[h * 64 + d];
                const float wv = Wv[h * 64 + d];
                const float4 p0 = *(const float4*)(&bufB[h][0]);
                const float4 p1 = *(const float4*)(&bufB[h][4]);
                ak[0] = fmaf(p0.x, wk, ak[0]); av[0] = fmaf(p0.x, wv, av[0]);
                ak[1] = fmaf(p0.y, wk, ak[1]); av[1] = fmaf(p0.y, wv, av[1]);
                ak[2] = fmaf(p0.z, wk, ak[2]); av[2] = fmaf(p0.z, wv, av[2]);
                ak[3] = fmaf(p0.w, wk, ak[3]); av[3] = fmaf(p0.w, wv, av[3]);
                ak[4] = fmaf(p1.x, wk, ak[4]); av[4] = fmaf(p1.x, wv, av[4]);
                ak[5] = fmaf(p1.y, wk, ak[5]); av[5] = fmaf(p1.y, wv, av[5]);
                ak[6] = fmaf(p1.z, wk, ak[6]); av[6] = fmaf(p1.z, wv, av[6]);
                ak[7] = fmaf(p1.w, wk, ak[7]); av[7] = fmaf(p1.w, wv, av[7]);
            }
            #pragma unroll
            for (int kk = 0; kk < 8; kk++) {
                const float kf = fmaxf(ak[kk], 0.f);
                sV[k0 + kk][d] = av[kk];
                bufA[d][kk] = (kf - q) * fcr[kk];   // bufA safe: hid reads done pre-sync
            }
        }
        __syncthreads();

        // ---- wh = relu(rel @ Ww1 + bw1) ----
        {
            float acc[8];
            const float bb = bw1[d];
            #pragma unroll
            for (int kk = 0; kk < 8; kk++) acc[kk] = bb;
            #pragma unroll
            for (int h = 0; h < 64; h++) {
                const float w = Ww1[h * 64 + d];
                const float4 r0 = *(const float4*)(&bufA[h][0]);
                const float4 r1 = *(const float4*)(&bufA[h][4]);
                acc[0] = fmaf(r0.x, w, acc[0]); acc[1] = fmaf(r0.y, w, acc[1]);
                acc[2] = fmaf(r0.z, w, acc[2]); acc[3] = fmaf(r0.w, w, acc[3]);
                acc[4] = fmaf(r1.x, w, acc[4]); acc[5] = fmaf(r1.y, w, acc[5]);
                acc[6] = fmaf(r1.z, w, acc[6]); acc[7] = fmaf(r1.w, w, acc[7]);
            }
            #pragma unroll
            for (int kk = 0; kk < 8; kk++)
                bufB[d][kk] = fmaxf(acc[kk], 0.f);
        }
        __syncthreads();

        // ---- w_pre = wh @ Ww2 + bw2 ----
        {
            float acc[8];
            const float bb = bw2[d];
            #pragma unroll
            for (int kk = 0; kk < 8; kk++) acc[kk] = bb;
            #pragma unroll
            for (int h = 0; h < 64; h++) {
                const float w = Ww2[h * 64 + d];
                const float4 r0 = *(const float4*)(&bufB[h][0]);
                const float4 r1 = *(const float4*)(&bufB[h][4]);
                acc[0] = fmaf(r0.x, w, acc[0]); acc[1] = fmaf(r0.y, w, acc[1]);
                acc[2] = fmaf(r0.z, w, acc[2]); acc[3] = fmaf(r0.w, w, acc[3]);
                acc[4] = fmaf(r1.x, w, acc[4]); acc[5] = fmaf(r1.y, w, acc[5]);
                acc[6] = fmaf(r1.z, w, acc[6]); acc[7] = fmaf(r1.w, w, acc[7]);
            }
            #pragma unroll
            for (int kk = 0; kk < 8; kk++)
                sW[k0 + kk][d] = acc[kk];
        }
        __syncthreads();
    }

    // ---- sparsemax over k (per d), Michelot fixed point (no sort) ----
    float z[32];
    #pragma unroll
    for (int k = 0; k < 32; k++) z[k] = sW[k][d];

    float s = 0.f;
    #pragma unroll
    for (int k = 0; k < 32; k++) s += z[k];
    float cnt = 32.f;
    float tau = (s - 1.f) / cnt;
    for (int it = 0; it < 32; it++) {
        float ns = 0.f, nc = 0.f;
        #pragma unroll
        for (int k = 0; k < 32; k++) {
            if (z[k] > tau) { ns += z[k]; nc += 1.f; }
        }
        if (nc == cnt) break;             // support stable (nested sets) -> tau is fixed point
        cnt = nc;
        tau = (ns - 1.f) / nc;
    }

    float attn = 0.f;
    #pragma unroll
    for (int k = 0; k < 32; k++)
        attn += fmaxf(z[k] - tau, 0.f) * sV[k][d];

    // ---- x_att = 2*feats + attn; LayerNorm ----
    float x = fmaf(2.f, sF[d], attn);
    float s1 = x;
    #pragma unroll
    for (int off = 16; off > 0; off >>= 1) s1 += __shfl_xor_sync(0xffffffffu, s1, off);
    if ((d & 31) == 0) red[d >> 5] = s1;
    __syncthreads();
    const float mean = (red[0] + red[1]) * (1.f / 64.f);
    const float c = x - mean;
    float s2 = c * c;
    #pragma unroll
    for (int off = 16; off > 0; off >>= 1) s2 += __shfl_xor_sync(0xffffffffu, s2, off);
    if ((d & 31) == 0) red[2 + (d >> 5)] = s2;
    __syncthreads();
    const float var = (red[2] + red[3]) * (1.f / 64.f);
    g_h[i * 64 + d] = fmaf(g_att[d] * c, rsqrtf(var + 1e-5f), b_att[d]);
}

__global__ __launch_bounds__(64, 8)
void gcn_kernel(const float* __restrict__ coords,
                const float* __restrict__ Wsg, const float* __restrict__ bsg,
                const float* __restrict__ Wf,  const float* __restrict__ bf,
                const float* __restrict__ g_ff, const float* __restrict__ b_ff,
                const int* __restrict__ knn,
                float* __restrict__ out)
{
    const int i = blockIdx.x;
    const int d = threadIdx.x;

    __shared__ float sAgg[68];
    __shared__ int   sIdx[32];
    __shared__ float s1buf[64];
    __shared__ float red[4];

    if (d < 32) sIdx[d] = knn[i * 33 + 1 + d];
    __syncthreads();

    const float hd = g_h[i * 64 + d];
    float a = hd;
    #pragma unroll 8
    for (int k = 0; k < 32; k++) a += g_h[sIdx[k] * 64 + d];
    sAgg[d] = a * (1.f / 33.f);
    if (d < 3) {
        float cc = coords[i * 3 + d];
        for (int k = 0; k < 32; k++) cc += coords[sIdx[k] * 3 + d];
        sAgg[64 + d] = cc * (1.f / 33.f);
    }
    __syncthreads();

    // x1 = relu(agg @ Wsg + bsg)
    float x1 = bsg[d];
    #pragma unroll
    for (int j = 0; j < 67; j++) x1 = fmaf(sAgg[j], Wsg[j * 64 + d], x1);
    s1buf[d] = fmaxf(x1, 0.f);
    __syncthreads();

    // x2 = x1 @ Wf + bf ; x = x2 + h ; LayerNorm
    float x2 = bf[d];
    #pragma unroll
    for (int j = 0; j < 64; j++) x2 = fmaf(s1buf[j], Wf[j * 64 + d], x2);
    const float x = x2 + hd;

    float r1 = x;
    #pragma unroll
    for (int off = 16; off > 0; off >>= 1) r1 += __shfl_xor_sync(0xffffffffu, r1, off);
    if ((d & 31) == 0) red[d >> 5] = r1;
    __syncthreads();
    const float mean = (red[0] + red[1]) * (1.f / 64.f);
    const float c = x - mean;
    float r2 = c * c;
    #pragma unroll
    for (int off = 16; off > 0; off >>= 1) r2 += __shfl_xor_sync(0xffffffffu, r2, off);
    if ((d & 31) == 0) red[2 + (d >> 5)] = r2;
    __syncthreads();
    const float var = (red[2] + red[3]) * (1.f / 64.f);
    out[i * 64 + d] = fmaf(g_ff[d] * c, rsqrtf(var + 1e-5f), b_ff[d]);
}

extern "C" void kernel_launch(void* const* d_in, const int* in_sizes, int n_in,
                              void* d_out, int out_size)
{
    const float* coords = (const float*)d_in[0];
    const float* feats  = (const float*)d_in[1];
    const float* Wq     = (const float*)d_in[2];
    const float* bq     = (const float*)d_in[3];
    const float* Wk     = (const float*)d_in[4];
    const float* bk     = (const float*)d_in[5];
    const float* Wv     = (const float*)d_in[6];
    const float* bv     = (const float*)d_in[7];
    const float* Wl1    = (const float*)d_in[8];
    const float* bl1    = (const float*)d_in[9];
    const float* Wl2    = (const float*)d_in[10];
    const float* bl2    = (const float*)d_in[11];
    const float* Ww1    = (const float*)d_in[12];
    const float* bw1    = (const float*)d_in[13];
    const float* Ww2    = (const float*)d_in[14];
    const float* bw2    = (const float*)d_in[15];
    const float* g_att  = (const float*)d_in[16];
    const float* b_att  = (const float*)d_in[17];
    const float* Wsg    = (const float*)d_in[18];
    const float* bsg    = (const float*)d_in[19];
    const float* Wf     = (const float*)d_in[20];
    const float* bf     = (const float*)d_in[21];
    const float* g_ff   = (const float*)d_in[22];
    const float* b_ff   = (const float*)d_in[23];
    const int*   knn    = (const int*)d_in[24];

    attn_kernel<<<NN, 64>>>(coords, feats, Wq, bq, Wk, bk, Wv, bv,
                            Wl1, bl1, Wl2, bl2, Ww1, bw1, Ww2, bw2,
                            g_att, b_att, knn);
    gcn_kernel<<<NN, 64>>>(coords, Wsg, bsg, Wf, bf, g_ff, b_ff, knn,
                           (float*)d_out);
}

// round 2
// speedup vs baseline: 1.1777x; 1.1777x over previous
#include <cuda_runtime.h>

#define NN 20000
#define DD 64
#define KK 32
#define RS 36   // smem row stride (floats): float4-aligned, conflict-free vec4 phases

// scratch for h (output of attention+LN1), read by the GCN kernel
__device__ float g_h[NN * DD];

#define FMA2(d_, a_, b_, c_) \
    asm("fma.rn.f32x2 %0, %1, %2, %3;" : "=l"(d_) : "l"(a_), "l"(b_), "l"(c_))

__device__ __forceinline__ unsigned long long pack2(float x, float y) {
    unsigned long long r;
    asm("mov.b64 %0, {%1, %2};" : "=l"(r) : "f"(x), "f"(y));
    return r;
}
__device__ __forceinline__ void unpack2(float& x, float& y, unsigned long long v) {
    asm("mov.b64 {%0, %1}, %2;" : "=f"(x), "=f"(y) : "l"(v));
}

// One h-sweep: acc[k] += ROW[h][k] * W[h*64+d], k = 0..31, packed f32x2.
// ROW rows must be 16B aligned (RS % 4 == 0).
#define GEMM_SWEEP(ACC, ROWBUF, WPTR, BIAS)                                   \
    {                                                                         \
        const unsigned long long binit = pack2((BIAS), (BIAS));               \
        _Pragma("unroll")                                                     \
        for (int j = 0; j < 16; j++) ACC[j] = binit;                          \
        _Pragma("unroll 8")                                                   \
        for (int h = 0; h < 64; h++) {                                        \
            const float w = (WPTR)[h * 64 + d];                               \
            const unsigned long long ww = pack2(w, w);                        \
            const ulonglong2* row = (const ulonglong2*)&ROWBUF[h][0];         \
            _Pragma("unroll")                                                 \
            for (int j = 0; j < 8; j++) {                                     \
                ulonglong2 v = row[j];                                        \
                FMA2(ACC[2 * j],     v.x, ww, ACC[2 * j]);                    \
                FMA2(ACC[2 * j + 1], v.y, ww, ACC[2 * j + 1]);                \
            }                                                                 \
        }                                                                     \
    }

#define UNPACK_ACC(R, ACC)                                                    \
    _Pragma("unroll")                                                         \
    for (int j = 0; j < 16; j++) unpack2(R[2 * j], R[2 * j + 1], ACC[j]);

#define STORE_ROW(ROWBUF, R)                                                  \
    {                                                                         \
        float4* dst = (float4*)&ROWBUF[d][0];                                 \
        _Pragma("unroll")                                                     \
        for (int j = 0; j < 8; j++) {                                         \
            float4 v;                                                         \
            v.x = R[4 * j]; v.y = R[4 * j + 1];                               \
            v.z = R[4 * j + 2]; v.w = R[4 * j + 3];                           \
            dst[j] = v;                                                       \
        }                                                                     \
    }

__global__ __launch_bounds__(64, 7)
void attn_kernel(const float* __restrict__ coords,
                 const float* __restrict__ feats,
                 const float* __restrict__ Wq, const float* __restrict__ bq,
                 const float* __restrict__ Wk, const float* __restrict__ bk,
                 const float* __restrict__ Wv, const float* __restrict__ bv,
                 const float* __restrict__ Wl1, const float* __restrict__ bl1,
                 const float* __restrict__ Wl2, const float* __restrict__ bl2,
                 const float* __restrict__ Ww1, const float* __restrict__ bw1,
                 const float* __restrict__ Ww2, const float* __restrict__ bw2,
                 const float* __restrict__ g_att, const float* __restrict__ b_att,
                 const int* __restrict__ knn)
{
    const int i = blockIdx.x;
    const int d = threadIdx.x;

    __shared__ float sA[64][RS];   // hid  -> wh
    __shared__ float sB[64][RS];   // fc   -> rel
    __shared__ float sC[64][RS];   // pe
    __shared__ float sF[64];       // feats[i]
    __shared__ float sC0[3];       // coords[i]
    __shared__ int   sIdx[32];     // knn[i, 0:32]
    __shared__ float sCoord[32][3];
    __shared__ float red[4];

    sF[d] = feats[i * 64 + d];
    if (d < 32) sIdx[d] = knn[i * 33 + d];
    if (d < 3)  sC0[d]  = coords[i * 3 + d];
    __syncthreads();

    for (int t = d; t < 96; t += 64)
        sCoord[t / 3][t % 3] = coords[sIdx[t / 3] * 3 + (t % 3)];

    // Q[d] = relu(feats[i] @ Wq + bq)[d]
    float q = bq[d];
    #pragma unroll 8
    for (int j = 0; j < 64; j++) q = fmaf(sF[j], Wq[j * 64 + d], q);
    q = fmaxf(q, 0.f);
    __syncthreads();   // sCoord ready

    // ---- hid[d][k] = relu(diff @ Wl1 + bl1) -> sA ----
    {
        float r[32];
        const float b0 = bl1[d];
        const float w0 = Wl1[d], w1 = Wl1[64 + d], w2 = Wl1[128 + d];
        #pragma unroll
        for (int k = 0; k < 32; k++) {
            const float dx = sCoord[k][0] - sC0[0];
            const float dy = sCoord[k][1] - sC0[1];
            const float dz = sCoord[k][2] - sC0[2];
            r[k] = fmaxf(fmaf(dx, w0, fmaf(dy, w1, fmaf(dz, w2, b0))), 0.f);
        }
        STORE_ROW(sA, r);
    }
    __syncthreads();

    unsigned long long acc[16];

    // ---- fc = hid @ Wl2 + bl2 -> sB ; pe = fc + feats[idx] -> sC ----
    {
        GEMM_SWEEP(acc, sA, Wl2, bl2[d]);
        float r[32], p[32];
        UNPACK_ACC(r, acc);
        #pragma unroll
        for (int k = 0; k < 32; k++)
            p[k] = r[k] + feats[sIdx[k] * 64 + d];
        STORE_ROW(sB, r);
        STORE_ROW(sC, p);
    }
    __syncthreads();

    // ---- Kf = relu(pe @ Wk + bk); rel = (Kf - Q)*fc -> sB (in place) ----
    {
        GEMM_SWEEP(acc, sC, Wk, bk[d]);
        float r[32];
        UNPACK_ACC(r, acc);
        const float4* fcv = (const float4*)&sB[d][0];
        float4 f[8];
        #pragma unroll
        for (int j = 0; j < 8; j++) f[j] = fcv[j];
        #pragma unroll
        for (int j = 0; j < 8; j++) {
            r[4 * j]     = (fmaxf(r[4 * j],     0.f) - q) * f[j].x;
            r[4 * j + 1] = (fmaxf(r[4 * j + 1], 0.f) - q) * f[j].y;
            r[4 * j + 2] = (fmaxf(r[4 * j + 2], 0.f) - q) * f[j].z;
            r[4 * j + 3] = (fmaxf(r[4 * j + 3], 0.f) - q) * f[j].w;
        }
        STORE_ROW(sB, r);
    }
    __syncthreads();

    // ---- wh = relu(rel @ Ww1 + bw1) -> sA ----
    {
        GEMM_SWEEP(acc, sB, Ww1, bw1[d]);
        float r[32];
        UNPACK_ACC(r, acc);
        #pragma unroll
        for (int k = 0; k < 32; k++) r[k] = fmaxf(r[k], 0.f);
        STORE_ROW(sA, r);
    }
    __syncthreads();

    // ---- z = wh @ Ww2 + bw2 (kept in registers: z[k] = w_pre[k][d]) ----
    float z[32];
    {
        GEMM_SWEEP(acc, sA, Ww2, bw2[d]);
        UNPACK_ACC(z, acc);
    }

    // ---- sparsemax over k (per d), Michelot fixed point ----
    float s = 0.f;
    #pragma unroll
    for (int k = 0; k < 32; k++) s += z[k];
    float cnt = 32.f;
    float tau = (s - 1.f) / cnt;
    for (int it = 0; it < 32; it++) {
        float ns = 0.f, nc = 0.f;
        #pragma unroll
        for (int k = 0; k < 32; k++) {
            if (z[k] > tau) { ns += z[k]; nc += 1.f; }
        }
        if (nc == cnt) break;   // support stable (nested sets) -> fixed point
        cnt = nc;
        tau = (ns - 1.f) / nc;
    }

    // ---- V = pe @ Wv + bv (registers), attn = sum_k p[k] * V[k] ----
    float attn = 0.f;
    {
        GEMM_SWEEP(acc, sC, Wv, bv[d]);
        float v[32];
        UNPACK_ACC(v, acc);
        #pragma unroll
        for (int k = 0; k < 32; k++)
            attn = fmaf(fmaxf(z[k] - tau, 0.f), v[k], attn);
    }

    // ---- x_att = 2*feats + attn; LayerNorm ----
    float x = fmaf(2.f, sF[d], attn);
    float s1 = x;
    #pragma unroll
    for (int off = 16; off > 0; off >>= 1) s1 += __shfl_xor_sync(0xffffffffu, s1, off);
    if ((d & 31) == 0) red[d >> 5] = s1;
    __syncthreads();
    const float mean = (red[0] + red[1]) * (1.f / 64.f);
    const float c = x - mean;
    float s2 = c * c;
    #pragma unroll
    for (int off = 16; off > 0; off >>= 1) s2 += __shfl_xor_sync(0xffffffffu, s2, off);
    if ((d & 31) == 0) red[2 + (d >> 5)] = s2;
    __syncthreads();
    const float var = (red[2] + red[3]) * (1.f / 64.f);
    g_h[i * 64 + d] = fmaf(g_att[d] * c, rsqrtf(var + 1e-5f), b_att[d]);
}

__global__ __launch_bounds__(64, 8)
void gcn_kernel(const float* __restrict__ coords,
                const float* __restrict__ Wsg, const float* __restrict__ bsg,
                const float* __restrict__ Wf,  const float* __restrict__ bf,
                const float* __restrict__ g_ff, const float* __restrict__ b_ff,
                const int* __restrict__ knn,
                float* __restrict__ out)
{
    const int i = blockIdx.x;
    const int d = threadIdx.x;

    __shared__ float sAgg[68];
    __shared__ int   sIdx[32];
    __shared__ float s1buf[64];
    __shared__ float red[4];

    if (d < 32) sIdx[d] = knn[i * 33 + 1 + d];
    __syncthreads();

    const float hd = g_h[i * 64 + d];
    float a = hd;
    #pragma unroll 8
    for (int k = 0; k < 32; k++) a += g_h[sIdx[k] * 64 + d];
    sAgg[d] = a * (1.f / 33.f);
    if (d < 3) {
        float cc = coords[i * 3 + d];
        for (int k = 0; k < 32; k++) cc += coords[sIdx[k] * 3 + d];
        sAgg[64 + d] = cc * (1.f / 33.f);
    }
    __syncthreads();

    // x1 = relu(agg @ Wsg + bsg)
    float x1 = bsg[d];
    #pragma unroll
    for (int j = 0; j < 67; j++) x1 = fmaf(sAgg[j], Wsg[j * 64 + d], x1);
    s1buf[d] = fmaxf(x1, 0.f);
    __syncthreads();

    // x2 = x1 @ Wf + bf ; x = x2 + h ; LayerNorm
    float x2 = bf[d];
    #pragma unroll
    for (int j = 0; j < 64; j++) x2 = fmaf(s1buf[j], Wf[j * 64 + d], x2);
    const float x = x2 + hd;

    float r1 = x;
    #pragma unroll
    for (int off = 16; off > 0; off >>= 1) r1 += __shfl_xor_sync(0xffffffffu, r1, off);
    if ((d & 31) == 0) red[d >> 5] = r1;
    __syncthreads();
    const float mean = (red[0] + red[1]) * (1.f / 64.f);
    const float c = x - mean;
    float r2 = c * c;
    #pragma unroll
    for (int off = 16; off > 0; off >>= 1) r2 += __shfl_xor_sync(0xffffffffu, r2, off);
    if ((d & 31) == 0) red[2 + (d >> 5)] = r2;
    __syncthreads();
    const float var = (red[2] + red[3]) * (1.f / 64.f);
    out[i * 64 + d] = fmaf(g_ff[d] * c, rsqrtf(var + 1e-5f), b_ff[d]);
}

extern "C" void kernel_launch(void* const* d_in, const int* in_sizes, int n_in,
                              void* d_out, int out_size)
{
    const float* coords = (const float*)d_in[0];
    const float* feats  = (const float*)d_in[1];
    const float* Wq     = (const float*)d_in[2];
    const float* bq     = (const float*)d_in[3];
    const float* Wk     = (const float*)d_in[4];
    const float* bk     = (const float*)d_in[5];
    const float* Wv     = (const float*)d_in[6];
    const float* bv     = (const float*)d_in[7];
    const float* Wl1    = (const float*)d_in[8];
    const float* bl1    = (const float*)d_in[9];
    const float* Wl2    = (const float*)d_in[10];
    const float* bl2    = (const float*)d_in[11];
    const float* Ww1    = (const float*)d_in[12];
    const float* bw1    = (const float*)d_in[13];
    const float* Ww2    = (const float*)d_in[14];
    const float* bw2    = (const float*)d_in[15];
    const float* g_att  = (const float*)d_in[16];
    const float* b_att  = (const float*)d_in[17];
    const float* Wsg    = (const float*)d_in[18];
    const float* bsg    = (const float*)d_in[19];
    const float* Wf     = (const float*)d_in[20];
    const float* bf     = (const float*)d_in[21];
    const float* g_ff   = (const float*)d_in[22];
    const float* b_ff   = (const float*)d_in[23];
    const int*   knn    = (const int*)d_in[24];

    attn_kernel<<<NN, 64>>>(coords, feats, Wq, bq, Wk, bk, Wv, bv,
                            Wl1, bl1, Wl2, bl2, Ww1, bw1, Ww2, bw2,
                            g_att, b_att, knn);
    gcn_kernel<<<NN, 64>>>(coords, Wsg, bsg, Wf, bf, g_ff, b_ff, knn,
                           (float*)d_out);
}

// round 3
// speedup vs baseline: 1.1781x; 1.0004x over previous
#include <cuda_runtime.h>

#define NN 20000
#define DD 64
#define KK 32
#define RS 36   // smem row stride (floats): float4-aligned, conflict-free vec4 phases

// scratch for h (output of attention+LN1), read by the GCN kernel
__device__ float g_h[NN * DD];

#define FMA2(d_, a_, b_, c_) \
    asm("fma.rn.f32x2 %0, %1, %2, %3;" : "=l"(d_) : "l"(a_), "l"(b_), "l"(c_))

__device__ __forceinline__ unsigned long long pack2(float x, float y) {
    unsigned long long r;
    asm("mov.b64 %0, {%1, %2};" : "=l"(r) : "f"(x), "f"(y));
    return r;
}
__device__ __forceinline__ void unpack2(float& x, float& y, unsigned long long v) {
    asm("mov.b64 {%0, %1}, %2;" : "=f"(x), "=f"(y) : "l"(v));
}

// One h-sweep: acc[k] += ROW[h][k] * W[h*64+d], k = 0..31, packed f32x2.
// ROW rows must be 16B aligned (RS % 4 == 0).
#define GEMM_SWEEP(ACC, ROWBUF, WPTR, BIAS)                                   \
    {                                                                         \
        const unsigned long long binit = pack2((BIAS), (BIAS));               \
        _Pragma("unroll")                                                     \
        for (int j = 0; j < 16; j++) ACC[j] = binit;                          \
        _Pragma("unroll 8")                                                   \
        for (int h = 0; h < 64; h++) {                                        \
            const float w = (WPTR)[h * 64 + d];                               \
            const unsigned long long ww = pack2(w, w);                        \
            const ulonglong2* row = (const ulonglong2*)&ROWBUF[h][0];         \
            _Pragma("unroll")                                                 \
            for (int j = 0; j < 8; j++) {                                     \
                ulonglong2 v = row[j];                                        \
                FMA2(ACC[2 * j],     v.x, ww, ACC[2 * j]);                    \
                FMA2(ACC[2 * j + 1], v.y, ww, ACC[2 * j + 1]);                \
            }                                                                 \
        }                                                                     \
    }

#define UNPACK_ACC(R, ACC)                                                    \
    _Pragma("unroll")                                                         \
    for (int j = 0; j < 16; j++) unpack2(R[2 * j], R[2 * j + 1], ACC[j]);

#define STORE_ROW(ROWBUF, R)                                                  \
    {                                                                         \
        float4* dst = (float4*)&ROWBUF[d][0];                                 \
        _Pragma("unroll")                                                     \
        for (int j = 0; j < 8; j++) {                                         \
            float4 v;                                                         \
            v.x = R[4 * j]; v.y = R[4 * j + 1];                               \
            v.z = R[4 * j + 2]; v.w = R[4 * j + 3];                           \
            dst[j] = v;                                                       \
        }                                                                     \
    }

__global__ __launch_bounds__(64, 7)
void attn_kernel(const float* __restrict__ coords,
                 const float* __restrict__ feats,
                 const float* __restrict__ Wq, const float* __restrict__ bq,
                 const float* __restrict__ Wk, const float* __restrict__ bk,
                 const float* __restrict__ Wv, const float* __restrict__ bv,
                 const float* __restrict__ Wl1, const float* __restrict__ bl1,
                 const float* __restrict__ Wl2, const float* __restrict__ bl2,
                 const float* __restrict__ Ww1, const float* __restrict__ bw1,
                 const float* __restrict__ Ww2, const float* __restrict__ bw2,
                 const float* __restrict__ g_att, const float* __restrict__ b_att,
                 const int* __restrict__ knn)
{
    const int i = blockIdx.x;
    const int d = threadIdx.x;

    __shared__ float sA[64][RS];   // hid  -> wh
    __shared__ float sB[64][RS];   // fc   -> rel
    __shared__ float sC[64][RS];   // pe
    __shared__ float sF[64];       // feats[i]
    __shared__ float sC0[3];       // coords[i]
    __shared__ int   sIdx[32];     // knn[i, 0:32]
    __shared__ float sCoord[32][3];
    __shared__ float red[4];

    sF[d] = feats[i * 64 + d];
    if (d < 32) sIdx[d] = knn[i * 33 + d];
    if (d < 3)  sC0[d]  = coords[i * 3 + d];
    __syncthreads();

    for (int t = d; t < 96; t += 64)
        sCoord[t / 3][t % 3] = coords[sIdx[t / 3] * 3 + (t % 3)];

    // Q[d] = relu(feats[i] @ Wq + bq)[d]
    float q = bq[d];
    #pragma unroll 8
    for (int j = 0; j < 64; j++) q = fmaf(sF[j], Wq[j * 64 + d], q);
    q = fmaxf(q, 0.f);
    __syncthreads();   // sCoord ready

    // ---- hid[d][k] = relu(diff @ Wl1 + bl1) -> sA ----
    {
        float r[32];
        const float b0 = bl1[d];
        const float w0 = Wl1[d], w1 = Wl1[64 + d], w2 = Wl1[128 + d];
        #pragma unroll
        for (int k = 0; k < 32; k++) {
            const float dx = sCoord[k][0] - sC0[0];
            const float dy = sCoord[k][1] - sC0[1];
            const float dz = sCoord[k][2] - sC0[2];
            r[k] = fmaxf(fmaf(dx, w0, fmaf(dy, w1, fmaf(dz, w2, b0))), 0.f);
        }
        STORE_ROW(sA, r);
    }
    __syncthreads();

    unsigned long long acc[16];

    // ---- fc = hid @ Wl2 + bl2 -> sB ; pe = fc + feats[idx] -> sC ----
    {
        GEMM_SWEEP(acc, sA, Wl2, bl2[d]);
        float r[32], p[32];
        UNPACK_ACC(r, acc);
        #pragma unroll
        for (int k = 0; k < 32; k++)
            p[k] = r[k] + feats[sIdx[k] * 64 + d];
        STORE_ROW(sB, r);
        STORE_ROW(sC, p);
    }
    __syncthreads();

    // ---- Kf = relu(pe @ Wk + bk); rel = (Kf - Q)*fc -> sB (in place) ----
    {
        GEMM_SWEEP(acc, sC, Wk, bk[d]);
        float r[32];
        UNPACK_ACC(r, acc);
        const float4* fcv = (const float4*)&sB[d][0];
        float4 f[8];
        #pragma unroll
        for (int j = 0; j < 8; j++) f[j] = fcv[j];
        #pragma unroll
        for (int j = 0; j < 8; j++) {
            r[4 * j]     = (fmaxf(r[4 * j],     0.f) - q) * f[j].x;
            r[4 * j + 1] = (fmaxf(r[4 * j + 1], 0.f) - q) * f[j].y;
            r[4 * j + 2] = (fmaxf(r[4 * j + 2], 0.f) - q) * f[j].z;
            r[4 * j + 3] = (fmaxf(r[4 * j + 3], 0.f) - q) * f[j].w;
        }
        STORE_ROW(sB, r);
    }
    __syncthreads();

    // ---- wh = relu(rel @ Ww1 + bw1) -> sA ----
    {
        GEMM_SWEEP(acc, sB, Ww1, bw1[d]);
        float r[32];
        UNPACK_ACC(r, acc);
        #pragma unroll
        for (int k = 0; k < 32; k++) r[k] = fmaxf(r[k], 0.f);
        STORE_ROW(sA, r);
    }
    __syncthreads();

    // ---- z = wh @ Ww2 + bw2 (kept in registers: z[k] = w_pre[k][d]) ----
    float z[32];
    {
        GEMM_SWEEP(acc, sA, Ww2, bw2[d]);
        UNPACK_ACC(z, acc);
    }

    // ---- sparsemax over k (per d), Michelot fixed point ----
    float s = 0.f;
    #pragma unroll
    for (int k = 0; k < 32; k++) s += z[k];
    float cnt = 32.f;
    float tau = (s - 1.f) / cnt;
    for (int it = 0; it < 32; it++) {
        float ns = 0.f, nc = 0.f;
        #pragma unroll
        for (int k = 0; k < 32; k++) {
            if (z[k] > tau) { ns += z[k]; nc += 1.f; }
        }
        if (nc == cnt) break;   // support stable (nested sets) -> fixed point
        cnt = nc;
        tau = (ns - 1.f) / nc;
    }

    // ---- V = pe @ Wv + bv (registers), attn = sum_k p[k] * V[k] ----
    float attn = 0.f;
    {
        GEMM_SWEEP(acc, sC, Wv, bv[d]);
        float v[32];
        UNPACK_ACC(v, acc);
        #pragma unroll
        for (int k = 0; k < 32; k++)
            attn = fmaf(fmaxf(z[k] - tau, 0.f), v[k], attn);
    }

    // ---- x_att = 2*feats + attn; LayerNorm ----
    float x = fmaf(2.f, sF[d], attn);
    float s1 = x;
    #pragma unroll
    for (int off = 16; off > 0; off >>= 1) s1 += __shfl_xor_sync(0xffffffffu, s1, off);
    if ((d & 31) == 0) red[d >> 5] = s1;
    __syncthreads();
    const float mean = (red[0] + red[1]) * (1.f / 64.f);
    const float c = x - mean;
    float s2 = c * c;
    #pragma unroll
    for (int off = 16; off > 0; off >>= 1) s2 += __shfl_xor_sync(0xffffffffu, s2, off);
    if ((d & 31) == 0) red[2 + (d >> 5)] = s2;
    __syncthreads();
    const float var = (red[2] + red[3]) * (1.f / 64.f);
    g_h[i * 64 + d] = fmaf(g_att[d] * c, rsqrtf(var + 1e-5f), b_att[d]);
}

__global__ __launch_bounds__(64, 8)
void gcn_kernel(const float* __restrict__ coords,
                const float* __restrict__ Wsg, const float* __restrict__ bsg,
                const float* __restrict__ Wf,  const float* __restrict__ bf,
                const float* __restrict__ g_ff, const float* __restrict__ b_ff,
                const int* __restrict__ knn,
                float* __restrict__ out)
{
    const int i = blockIdx.x;
    const int d = threadIdx.x;

    __shared__ float sAgg[68];
    __shared__ int   sIdx[32];
    __shared__ float s1buf[64];
    __shared__ float red[4];

    if (d < 32) sIdx[d] = knn[i * 33 + 1 + d];
    __syncthreads();

    const float hd = g_h[i * 64 + d];
    float a = hd;
    #pragma unroll 8
    for (int k = 0; k < 32; k++) a += g_h[sIdx[k] * 64 + d];
    sAgg[d] = a * (1.f / 33.f);
    if (d < 3) {
        float cc = coords[i * 3 + d];
        for (int k = 0; k < 32; k++) cc += coords[sIdx[k] * 3 + d];
        sAgg[64 + d] = cc * (1.f / 33.f);
    }
    __syncthreads();

    // x1 = relu(agg @ Wsg + bsg)
    float x1 = bsg[d];
    #pragma unroll
    for (int j = 0; j < 67; j++) x1 = fmaf(sAgg[j], Wsg[j * 64 + d], x1);
    s1buf[d] = fmaxf(x1, 0.f);
    __syncthreads();

    // x2 = x1 @ Wf + bf ; x = x2 + h ; LayerNorm
    float x2 = bf[d];
    #pragma unroll
    for (int j = 0; j < 64; j++) x2 = fmaf(s1buf[j], Wf[j * 64 + d], x2);
    const float x = x2 + hd;

    float r1 = x;
    #pragma unroll
    for (int off = 16; off > 0; off >>= 1) r1 += __shfl_xor_sync(0xffffffffu, r1, off);
    if ((d & 31) == 0) red[d >> 5] = r1;
    __syncthreads();
    const float mean = (red[0] + red[1]) * (1.f / 64.f);
    const float c = x - mean;
    float r2 = c * c;
    #pragma unroll
    for (int off = 16; off > 0; off >>= 1) r2 += __shfl_xor_sync(0xffffffffu, r2, off);
    if ((d & 31) == 0) red[2 + (d >> 5)] = r2;
    __syncthreads();
    const float var = (red[2] + red[3]) * (1.f / 64.f);
    out[i * 64 + d] = fmaf(g_ff[d] * c, rsqrtf(var + 1e-5f), b_ff[d]);
}

extern "C" void kernel_launch(void* const* d_in, const int* in_sizes, int n_in,
                              void* d_out, int out_size)
{
    const float* coords = (const float*)d_in[0];
    const float* feats  = (const float*)d_in[1];
    const float* Wq     = (const float*)d_in[2];
    const float* bq     = (const float*)d_in[3];
    const float* Wk     = (const float*)d_in[4];
    const float* bk     = (const float*)d_in[5];
    const float* Wv     = (const float*)d_in[6];
    const float* bv     = (const float*)d_in[7];
    const float* Wl1    = (const float*)d_in[8];
    const float* bl1    = (const float*)d_in[9];
    const float* Wl2    = (const float*)d_in[10];
    const float* bl2    = (const float*)d_in[11];
    const float* Ww1    = (const float*)d_in[12];
    const float* bw1    = (const float*)d_in[13];
    const float* Ww2    = (const float*)d_in[14];
    const float* bw2    = (const float*)d_in[15];
    const float* g_att  = (const float*)d_in[16];
    const float* b_att  = (const float*)d_in[17];
    const float* Wsg    = (const float*)d_in[18];
    const float* bsg    = (const float*)d_in[19];
    const float* Wf     = (const float*)d_in[20];
    const float* bf     = (const float*)d_in[21];
    const float* g_ff   = (const float*)d_in[22];
    const float* b_ff   = (const float*)d_in[23];
    const int*   knn    = (const int*)d_in[24];

    attn_kernel<<<NN, 64>>>(coords, feats, Wq, bq, Wk, bk, Wv, bv,
                            Wl1, bl1, Wl2, bl2, Ww1, bw1, Ww2, bw2,
                            g_att, b_att, knn);
    gcn_kernel<<<NN, 64>>>(coords, Wsg, bsg, Wf, bf, g_ff, b_ff, knn,
                           (float*)d_out);
}

// round 6
// speedup vs baseline: 2.6167x; 2.2210x over previous
#include <cuda_runtime.h>
#include <cstdint>

#define NN 20000
// smem float offsets
#define OFF_WBUF0 0
#define OFF_WBUF1 4096
#define OFF_FW    8192    /* feats tile [4][32][68] ; later zT [256][36] */
#define OFF_FN    17408
#define OFF_Q     17664   /* Q, later tau */
#define OFF_BIAS  17920
#define OFF_WL1   18304
#define OFF_C0    18560
#define OFF_CW    18576
#define OFF_IDX   18960
#define SM_FLOATS 19088
#define SM_BYTES  (SM_FLOATS * 4)

#define B_BQ  0
#define B_BL2 64
#define B_BV  128
#define B_BK  192
#define B_BW1 256
#define B_BW2 320

__device__ float g_h[NN * 64];
__device__ uint4 g_wimg[5 * 1024];   // B-frag images: Wl2, Wv, Wk, Ww1, Ww2

__device__ __forceinline__ uint32_t smem_u32(const void* p) {
    uint32_t a;
    asm("{ .reg .u64 t; cvta.to.shared.u64 t, %1; cvt.u32.u64 %0, t; }" : "=r"(a) : "l"(p));
    return a;
}
__device__ __forceinline__ uint32_t pk2(float lo, float hi) {
    uint32_t r;
    asm("cvt.rn.bf16x2.f32 %0, %1, %2;" : "=r"(r) : "f"(hi), "f"(lo));
    return r;
}
#define BLO(u) __uint_as_float((u) << 16)
#define BHI(u) __uint_as_float((u) & 0xFFFF0000u)
__device__ __forceinline__ void split2(float x0, float x1, uint32_t& H, uint32_t& L) {
    H = pk2(x0, x1);
    L = pk2(x0 - BLO(H), x1 - BHI(H));
}
__device__ __forceinline__ void mma16816(float* d, uint32_t a0, uint32_t a1, uint32_t a2,
                                         uint32_t a3, uint32_t b0, uint32_t b1) {
    asm volatile("mma.sync.aligned.m16n8k16.row.col.f32.bf16.bf16.f32 "
        "{%0,%1,%2,%3}, {%4,%5,%6,%7}, {%8,%9}, {%0,%1,%2,%3};"
        : "+f"(d[0]), "+f"(d[1]), "+f"(d[2]), "+f"(d[3])
        : "r"(a0), "r"(a1), "r"(a2), "r"(a3), "r"(b0), "r"(b1));
}
#define CP16(dst, src) asm volatile("cp.async.cg.shared.global [%0], [%1], 16;" :: "r"(dst), "l"(src) : "memory")
#define CP_COMMIT()    asm volatile("cp.async.commit_group;" ::: "memory")
#define CP_WAIT(n)     asm volatile("cp.async.wait_group %0;" :: "n"(n) : "memory")

#define PREFETCH(IMG)                                                          \
    {                                                                          \
        const uint4* src = g_wimg + (IMG) * 1024;                              \
        uint32_t dst = sbase + ((IMG) & 1 ? OFF_WBUF1 : OFF_WBUF0) * 4;        \
        _Pragma("unroll")                                                      \
        for (int t = 0; t < 8; t++) CP16(dst + (tid + t * 128) * 16, src + tid + t * 128); \
        CP_COMMIT();                                                           \
    }

__device__ __forceinline__ void run_gemm(const uint4* __restrict__ Wb, int lane,
                                         const uint32_t AH[2][4][4],
                                         const uint32_t AL[2][4][4],
                                         float D[2][8][4]) {
    #pragma unroll
    for (int mt = 0; mt < 2; mt++)
        #pragma unroll
        for (int nt = 0; nt < 8; nt++)
            #pragma unroll
            for (int e = 0; e < 4; e++) D[mt][nt][e] = 0.f;
    #pragma unroll
    for (int nt = 0; nt < 8; nt++)
        #pragma unroll
        for (int kt = 0; kt < 4; kt++) {
            uint4 b = Wb[(kt * 8 + nt) * 32 + lane];
            #pragma unroll
            for (int mt = 0; mt < 2; mt++) {
                mma16816(D[mt][nt], AH[mt][kt][0], AH[mt][kt][1], AH[mt][kt][2], AH[mt][kt][3], b.x, b.y);
                mma16816(D[mt][nt], AL[mt][kt][0], AL[mt][kt][1], AL[mt][kt][2], AL[mt][kt][3], b.x, b.y);
                mma16816(D[mt][nt], AH[mt][kt][0], AH[mt][kt][1], AH[mt][kt][2], AH[mt][kt][3], b.z, b.w);
            }
        }
}

// pack weights into per-lane B-fragment images (hi,hi,lo,lo per uint4)
__global__ void prep_kernel(const float* __restrict__ Wl2, const float* __restrict__ Wv,
                            const float* __restrict__ Wk, const float* __restrict__ Ww1,
                            const float* __restrict__ Ww2) {
    const int g = blockIdx.x;
    const float* W = (g == 0) ? Wl2 : (g == 1) ? Wv : (g == 2) ? Wk : (g == 3) ? Ww1 : Ww2;
    for (int e = threadIdx.x; e < 1024; e += blockDim.x) {
        int lane = e & 31, tile = e >> 5;
        int kt = tile >> 3, nt = tile & 7;
        int k0 = kt * 16 + (lane & 3) * 2;
        int n = nt * 8 + (lane >> 2);
        uint32_t h0, l0, h1, l1;
        split2(W[k0 * 64 + n], W[(k0 + 1) * 64 + n], h0, l0);
        split2(W[(k0 + 8) * 64 + n], W[(k0 + 9) * 64 + n], h1, l1);
        g_wimg[g * 1024 + tile * 32 + lane] = make_uint4(h0, h1, l0, l1);
    }
}

__global__ void __launch_bounds__(128, 2)
attn_kernel(const float* __restrict__ coords, const float* __restrict__ feats,
            const float* __restrict__ Wq, const float* __restrict__ bq,
            const float* __restrict__ bk, const float* __restrict__ bv,
            const float* __restrict__ Wl1, const float* __restrict__ bl1,
            const float* __restrict__ bl2,
            const float* __restrict__ bw1, const float* __restrict__ bw2,
            const float* __restrict__ g_att, const float* __restrict__ b_att,
            const int* __restrict__ knn)
{
    extern __shared__ float sm[];
    const int tid = threadIdx.x;
    const int w = tid >> 5, lane = tid & 31;
    const int gnode = blockIdx.x * 4 + w;
    const int i0 = blockIdx.x * 4;
    const uint32_t sbase = smem_u32(sm);
    int* sIdx = (int*)(sm + OFF_IDX);

    PREFETCH(0);   // Wl2 -> WBUF0

    sIdx[w * 32 + lane] = knn[gnode * 33 + lane];
    if (lane < 3) sm[OFF_C0 + w * 4 + lane] = coords[gnode * 3 + lane];
    __syncwarp();
    {
        int j = sIdx[w * 32 + lane];
        sm[OFF_CW + (w * 32 + lane) * 3 + 0] = coords[j * 3 + 0];
        sm[OFF_CW + (w * 32 + lane) * 3 + 1] = coords[j * 3 + 1];
        sm[OFF_CW + (w * 32 + lane) * 3 + 2] = coords[j * 3 + 2];
    }
    #pragma unroll
    for (int it = 0; it < 16; it++) {   // neighbor feats tile [w][32][68]
        int r = it * 2 + (lane >> 4), c4 = lane & 15;
        int j = sIdx[w * 32 + r];
        float4 v = ((const float4*)feats)[j * 16 + c4];
        *(float4*)&sm[OFF_FW + (w * 32 + r) * 68 + c4 * 4] = v;
    }
    sm[OFF_FN + tid]       = feats[i0 * 64 + tid];
    sm[OFF_FN + tid + 128] = feats[i0 * 64 + tid + 128];
    #pragma unroll
    for (int t = 0; t < 8; t++)   // raw Wq -> WBUF1
        ((float4*)(sm + OFF_WBUF1))[tid + t * 128] = ((const float4*)Wq)[tid + t * 128];
    for (int e = tid; e < 384; e += 128) {
        int s = e >> 6, c = e & 63;
        sm[OFF_BIAS + e] = (s == 0) ? bq[c] : (s == 1) ? bl2[c] : (s == 2) ? bv[c] :
                           (s == 3) ? bk[c] : (s == 4) ? bw1[c] : bw2[c];
    }
    if (tid < 128) sm[OFF_WL1 + tid] = Wl1[tid];
    if (tid < 64)  { sm[OFF_WL1 + 128 + tid] = Wl1[128 + tid]; sm[OFF_WL1 + 192 + tid] = bl1[tid]; }
    __syncthreads();

    // Q = relu(feats_node @ Wq + bq)
    #pragma unroll
    for (int p = 0; p < 2; p++) {
        int e = tid + p * 128, n2 = e >> 6, col = e & 63;
        float acc = sm[OFF_BIAS + B_BQ + col];
        #pragma unroll 8
        for (int j = 0; j < 64; j++)
            acc = fmaf(sm[OFF_FN + n2 * 64 + j], sm[OFF_WBUF1 + j * 64 + col], acc);
        sm[OFF_Q + e] = fmaxf(acc, 0.f);
    }

    // hid = relu(diff @ Wl1 + bl1) -> A frags
    uint32_t AH[2][4][4], AL[2][4][4];
    {
        float c0x = sm[OFF_C0 + w * 4], c0y = sm[OFF_C0 + w * 4 + 1], c0z = sm[OFF_C0 + w * 4 + 2];
        float dx[4], dy[4], dz[4];
        #pragma unroll
        for (int m = 0; m < 4; m++) {
            int row = (lane >> 2) + m * 8;
            dx[m] = sm[OFF_CW + (w * 32 + row) * 3 + 0] - c0x;
            dy[m] = sm[OFF_CW + (w * 32 + row) * 3 + 1] - c0y;
            dz[m] = sm[OFF_CW + (w * 32 + row) * 3 + 2] - c0z;
        }
        #pragma unroll
        for (int kt = 0; kt < 4; kt++)
            #pragma unroll
            for (int half = 0; half < 2; half++) {
                int cc = kt * 16 + 2 * (lane & 3) + 8 * half;
                float2 w0 = *(float2*)&sm[OFF_WL1 + cc];
                float2 w1 = *(float2*)&sm[OFF_WL1 + 64 + cc];
                float2 w2 = *(float2*)&sm[OFF_WL1 + 128 + cc];
                float2 bb = *(float2*)&sm[OFF_WL1 + 192 + cc];
                #pragma unroll
                for (int mt = 0; mt < 2; mt++)
                    #pragma unroll
                    for (int rs = 0; rs < 2; rs++) {
                        int m = mt * 2 + rs;
                        float h0 = fmaxf(fmaf(dx[m], w0.x, fmaf(dy[m], w1.x, fmaf(dz[m], w2.x, bb.x))), 0.f);
                        float h1 = fmaxf(fmaf(dx[m], w0.y, fmaf(dy[m], w1.y, fmaf(dz[m], w2.y, bb.y))), 0.f);
                        split2(h0, h1, AH[mt][kt][half * 2 + rs], AL[mt][kt][half * 2 + rs]);
                    }
            }
    }
    __syncthreads();         // all done reading WBUF1 (Q)
    PREFETCH(1);             // Wv -> WBUF1
    CP_WAIT(1);
    __syncthreads();

    float D[2][8][4], V[2][8][4];

    // ---- stage 0: fc = hid @ Wl2; pe = fc + bl2 + feats[j] -> A ----
    run_gemm((const uint4*)(sm + OFF_WBUF0), lane, AH, AL, D);
    #pragma unroll
    for (int mt = 0; mt < 2; mt++) {
        int rA = mt * 16 + (lane >> 2);
        #pragma unroll
        for (int nt = 0; nt < 8; nt++) {
            int cb = nt * 8 + 2 * (lane & 3);
            float2 b2 = *(float2*)&sm[OFF_BIAS + B_BL2 + cb];
            float2 fA = *(float2*)&sm[OFF_FW + (w * 32 + rA) * 68 + cb];
            float2 fB = *(float2*)&sm[OFF_FW + (w * 32 + rA + 8) * 68 + cb];
            split2(D[mt][nt][0] + b2.x + fA.x, D[mt][nt][1] + b2.y + fA.y,
                   AH[mt][nt >> 1][(nt & 1) * 2], AL[mt][nt >> 1][(nt & 1) * 2]);
            split2(D[mt][nt][2] + b2.x + fB.x, D[mt][nt][3] + b2.y + fB.y,
                   AH[mt][nt >> 1][(nt & 1) * 2 + 1], AL[mt][nt >> 1][(nt & 1) * 2 + 1]);
        }
    }
    __syncthreads();
    PREFETCH(2);   // Wk -> WBUF0
    CP_WAIT(1);
    __syncthreads();

    // ---- stage 1: V = pe @ Wv + bv ----
    run_gemm((const uint4*)(sm + OFF_WBUF1), lane, AH, AL, D);
    #pragma unroll
    for (int mt = 0; mt < 2; mt++)
        #pragma unroll
        for (int nt = 0; nt < 8; nt++) {
            int cb = nt * 8 + 2 * (lane & 3);
            float2 b2 = *(float2*)&sm[OFF_BIAS + B_BV + cb];
            V[mt][nt][0] = D[mt][nt][0] + b2.x; V[mt][nt][1] = D[mt][nt][1] + b2.y;
            V[mt][nt][2] = D[mt][nt][2] + b2.x; V[mt][nt][3] = D[mt][nt][3] + b2.y;
        }
    __syncthreads();
    PREFETCH(3);   // Ww1 -> WBUF1
    CP_WAIT(1);
    __syncthreads();

    // ---- stage 2: Kf = pe @ Wk; rel = (relu(Kf+bk) - Q) * (pe - feats[j]) -> A ----
    run_gemm((const uint4*)(sm + OFF_WBUF0), lane, AH, AL, D);
    #pragma unroll
    for (int mt = 0; mt < 2; mt++) {
        int rA = mt * 16 + (lane >> 2);
        #pragma unroll
        for (int nt = 0; nt < 8; nt++) {
            int cb = nt * 8 + 2 * (lane & 3);
            float2 b2 = *(float2*)&sm[OFF_BIAS + B_BK + cb];
            float2 q2 = *(float2*)&sm[OFF_Q + w * 64 + cb];
            float2 fA = *(float2*)&sm[OFF_FW + (w * 32 + rA) * 68 + cb];
            float2 fB = *(float2*)&sm[OFF_FW + (w * 32 + rA + 8) * 68 + cb];
            uint32_t H0 = AH[mt][nt >> 1][(nt & 1) * 2],     L0 = AL[mt][nt >> 1][(nt & 1) * 2];
            uint32_t H1 = AH[mt][nt >> 1][(nt & 1) * 2 + 1], L1 = AL[mt][nt >> 1][(nt & 1) * 2 + 1];
            float r0 = (fmaxf(D[mt][nt][0] + b2.x, 0.f) - q2.x) * (BLO(H0) + BLO(L0) - fA.x);
            float r1 = (fmaxf(D[mt][nt][1] + b2.y, 0.f) - q2.y) * (BHI(H0) + BHI(L0) - fA.y);
            float r2 = (fmaxf(D[mt][nt][2] + b2.x, 0.f) - q2.x) * (BLO(H1) + BLO(L1) - fB.x);
            float r3 = (fmaxf(D[mt][nt][3] + b2.y, 0.f) - q2.y) * (BHI(H1) + BHI(L1) - fB.y);
            split2(r0, r1, AH[mt][nt >> 1][(nt & 1) * 2],     AL[mt][nt >> 1][(nt & 1) * 2]);
            split2(r2, r3, AH[mt][nt >> 1][(nt & 1) * 2 + 1], AL[mt][nt >> 1][(nt & 1) * 2 + 1]);
        }
    }
    __syncthreads();
    PREFETCH(4);   // Ww2 -> WBUF0
    CP_WAIT(1);
    __syncthreads();

    // ---- stage 3: wh = relu(rel @ Ww1 + bw1) -> A ----
    run_gemm((const uint4*)(sm + OFF_WBUF1), lane, AH, AL, D);
    #pragma unroll
    for (int mt = 0; mt < 2; mt++)
        #pragma unroll
        for (int nt = 0; nt < 8; nt++) {
            int cb = nt * 8 + 2 * (lane & 3);
            float2 b2 = *(float2*)&sm[OFF_BIAS + B_BW1 + cb];
            split2(fmaxf(D[mt][nt][0] + b2.x, 0.f), fmaxf(D[mt][nt][1] + b2.y, 0.f),
                   AH[mt][nt >> 1][(nt & 1) * 2], AL[mt][nt >> 1][(nt & 1) * 2]);
            split2(fmaxf(D[mt][nt][2] + b2.x, 0.f), fmaxf(D[mt][nt][3] + b2.y, 0.f),
                   AH[mt][nt >> 1][(nt & 1) * 2 + 1], AL[mt][nt >> 1][(nt & 1) * 2 + 1]);
        }
    CP_WAIT(0);
    __syncthreads();

    // ---- stage 4: z = wh @ Ww2 + bw2 -> zT smem (overwrites feats tile) ----
    run_gemm((const uint4*)(sm + OFF_WBUF0), lane, AH, AL, D);
    __syncthreads();   // all FW reads done before overwrite
    #pragma unroll
    for (int mt = 0; mt < 2; mt++) {
        int rA = mt * 16 + (lane >> 2);
        #pragma unroll
        for (int nt = 0; nt < 8; nt++) {
            int cb = nt * 8 + 2 * (lane & 3);
            float2 b2 = *(float2*)&sm[OFF_BIAS + B_BW2 + cb];
            sm[OFF_FW + (w * 64 + cb)     * 36 + rA]     = D[mt][nt][0] + b2.x;
            sm[OFF_FW + (w * 64 + cb + 1) * 36 + rA]     = D[mt][nt][1] + b2.y;
            sm[OFF_FW + (w * 64 + cb)     * 36 + rA + 8] = D[mt][nt][2] + b2.x;
            sm[OFF_FW + (w * 64 + cb + 1) * 36 + rA + 8] = D[mt][nt][3] + b2.y;
        }
    }
    __syncthreads();

    // ---- sparsemax (Michelot fixed point): tau per (node,col) ----
    #pragma unroll
    for (int p = 0; p < 2; p++) {
        int q = tid + p * 128;
        float z[32];
        const float* zp = &sm[OFF_FW + q * 36];
        #pragma unroll
        for (int j = 0; j < 8; j++) {
            float4 v = *(const float4*)&zp[j * 4];
            z[4 * j] = v.x; z[4 * j + 1] = v.y; z[4 * j + 2] = v.z; z[4 * j + 3] = v.w;
        }
        float s = 0.f;
        #pragma unroll
        for (int k = 0; k < 32; k++) s += z[k];
        float cnt = 32.f, tau = (s - 1.f) / cnt;
        for (int it = 0; it < 32; it++) {
            float ns = 0.f, nc = 0.f;
            #pragma unroll
            for (int k = 0; k < 32; k++)
                if (z[k] > tau) { ns += z[k]; nc += 1.f; }
            if (nc == cnt) break;
            cnt = nc; tau = (ns - 1.f) / nc;
        }
        sm[OFF_Q + q] = tau;   // Q region reused
    }
    __syncthreads();

    // ---- attn = sum_k relu(z - tau) * V; x = 2*feats + attn; LayerNorm ----
    float part[16];
    #pragma unroll
    for (int j = 0; j < 16; j++) part[j] = 0.f;
    #pragma unroll
    for (int mt = 0; mt < 2; mt++) {
        int rA = mt * 16 + (lane >> 2);
        #pragma unroll
        for (int nt = 0; nt < 8; nt++) {
            int cb = nt * 8 + 2 * (lane & 3);
            float2 t2 = *(float2*)&sm[OFF_Q + w * 64 + cb];
            #pragma unroll
            for (int rs = 0; rs < 2; rs++) {
                int row = rA + rs * 8;
                float z0 = sm[OFF_FW + (w * 64 + cb)     * 36 + row];
                float z1 = sm[OFF_FW + (w * 64 + cb + 1) * 36 + row];
                part[nt * 2]     = fmaf(fmaxf(z0 - t2.x, 0.f), V[mt][nt][rs * 2],     part[nt * 2]);
                part[nt * 2 + 1] = fmaf(fmaxf(z1 - t2.y, 0.f), V[mt][nt][rs * 2 + 1], part[nt * 2 + 1]);
            }
        }
    }
    #pragma unroll
    for (int j = 0; j < 16; j++) {
        float v = part[j];
        v += __shfl_xor_sync(0xffffffffu, v, 4);
        v += __shfl_xor_sync(0xffffffffu, v, 8);
        v += __shfl_xor_sync(0xffffffffu, v, 16);
        part[j] = v;
    }
    float xs[16], tot = 0.f;
    #pragma unroll
    for (int j = 0; j < 16; j++) {
        int col = 8 * (j >> 1) + 2 * (lane & 3) + (j & 1);
        xs[j] = fmaf(2.f, sm[OFF_FN + w * 64 + col], part[j]);
        tot += xs[j];
    }
    #pragma unroll
    for (int off = 16; off > 0; off >>= 1) tot += __shfl_xor_sync(0xffffffffu, tot, off);
    const float mean = tot * (1.f / 512.f);
    float vt = 0.f;
    #pragma unroll
    for (int j = 0; j < 16; j++) { float c = xs[j] - mean; vt += c * c; }
    #pragma unroll
    for (int off = 16; off > 0; off >>= 1) vt += __shfl_xor_sync(0xffffffffu, vt, off);
    const float rsg = rsqrtf(vt * (1.f / 512.f) + 1e-5f);
    if ((lane >> 2) == 0) {
        #pragma unroll
        for (int j = 0; j < 16; j++) {
            int col = 8 * (j >> 1) + 2 * (lane & 3) + (j & 1);
            g_h[gnode * 64 + col] = fmaf(g_att[col] * (xs[j] - mean), rsg, b_att[col]);
        }
    }
}

__global__ __launch_bounds__(64, 8)
void gcn_kernel(const float* __restrict__ coords,
                const float* __restrict__ Wsg, const float* __restrict__ bsg,
                const float* __restrict__ Wf,  const float* __restrict__ bf,
                const float* __restrict__ g_ff, const float* __restrict__ b_ff,
                const int* __restrict__ knn,
                float* __restrict__ out)
{
    const int i = blockIdx.x;
    const int d = threadIdx.x;
    __shared__ float sAgg[68];
    __shared__ int   sIdx[32];
    __shared__ float s1buf[64];
    __shared__ float red[4];

    if (d < 32) sIdx[d] = knn[i * 33 + 1 + d];
    __syncthreads();

    const float hd = g_h[i * 64 + d];
    float a = hd;
    #pragma unroll 8
    for (int k = 0; k < 32; k++) a += g_h[sIdx[k] * 64 + d];
    sAgg[d] = a * (1.f / 33.f);
    if (d < 3) {
        float cc = coords[i * 3 + d];
        for (int k = 0; k < 32; k++) cc += coords[sIdx[k] * 3 + d];
        sAgg[64 + d] = cc * (1.f / 33.f);
    }
    __syncthreads();

    float x1 = bsg[d];
    #pragma unroll
    for (int j = 0; j < 67; j++) x1 = fmaf(sAgg[j], Wsg[j * 64 + d], x1);
    s1buf[d] = fmaxf(x1, 0.f);
    __syncthreads();

    float x2 = bf[d];
    #pragma unroll
    for (int j = 0; j < 64; j++) x2 = fmaf(s1buf[j], Wf[j * 64 + d], x2);
    const float x = x2 + hd;

    float r1 = x;
    #pragma unroll
    for (int off = 16; off > 0; off >>= 1) r1 += __shfl_xor_sync(0xffffffffu, r1, off);
    if ((d & 31) == 0) red[d >> 5] = r1;
    __syncthreads();
    const float mean = (red[0] + red[1]) * (1.f / 64.f);
    const float c = x - mean;
    float r2 = c * c;
    #pragma unroll
    for (int off = 16; off > 0; off >>= 1) r2 += __shfl_xor_sync(0xffffffffu, r2, off);
    if ((d & 31) == 0) red[2 + (d >> 5)] = r2;
    __syncthreads();
    const float var = (red[2] + red[3]) * (1.f / 64.f);
    out[i * 64 + d] = fmaf(g_ff[d] * c, rsqrtf(var + 1e-5f), b_ff[d]);
}

extern "C" void kernel_launch(void* const* d_in, const int* in_sizes, int n_in,
                              void* d_out, int out_size)
{
    const float* coords = (const float*)d_in[0];
    const float* feats  = (const float*)d_in[1];
    const float* Wq  = (const float*)d_in[2];
    const float* bq  = (const float*)d_in[3];
    const float* Wk  = (const float*)d_in[4];
    const float* bk  = (const float*)d_in[5];
    const float* Wv  = (const float*)d_in[6];
    const float* bv  = (const float*)d_in[7];
    const float* Wl1 = (const float*)d_in[8];
    const float* bl1 = (const float*)d_in[9];
    const float* Wl2 = (const float*)d_in[10];
    const float* bl2 = (const float*)d_in[11];
    const float* Ww1 = (const float*)d_in[12];
    const float* bw1 = (const float*)d_in[13];
    const float* Ww2 = (const float*)d_in[14];
    const float* bw2 = (const float*)d_in[15];
    const float* g_att = (const float*)d_in[16];
    const float* b_att = (const float*)d_in[17];
    const float* Wsg = (const float*)d_in[18];
    const float* bsg = (const float*)d_in[19];
    const float* Wf  = (const float*)d_in[20];
    const float* bf  = (const float*)d_in[21];
    const float* g_ff = (const float*)d_in[22];
    const float* b_ff = (const float*)d_in[23];
    const int*   knn  = (const int*)d_in[24];

    cudaFuncSetAttribute(attn_kernel, cudaFuncAttributeMaxDynamicSharedMemorySize, SM_BYTES);

    prep_kernel<<<5, 256>>>(Wl2, Wv, Wk, Ww1, Ww2);
    attn_kernel<<<NN / 4, 128, SM_BYTES>>>(coords, feats, Wq, bq, bk, bv,
                                           Wl1, bl1, bl2, bw1, bw2,
                                           g_att, b_att, knn);
    gcn_kernel<<<NN, 64>>>(coords, Wsg, bsg, Wf, bf, g_ff, b_ff, knn,
                           (float*)d_out);
}

// round 7
// speedup vs baseline: 4.3321x; 1.6556x over previous
#include <cuda_runtime.h>
#include <cuda_fp16.h>
#include <cstdint>

#define NN 20000
// smem float offsets
#define OFF_WBUF0 0        /* 2048 floats (8KB)  */
#define OFF_WBUF1 2048     /* 2048 */
#define OFF_FW    4096     /* feats [4][32][68]=8704 ; later zT [256][36]=9216 */
#define OFF_FN    13312    /* 256 */
#define OFF_Q     13568    /* 256 (Q, later tau) */
#define OFF_BIAS  13824    /* 384 */
#define OFF_WL1   14208    /* 256 */
#define OFF_C0    14464    /* 16 */
#define OFF_CW    14480    /* 384 */
#define OFF_IDX   14864    /* 128 */
#define SM_FLOATS 14992
#define SM_BYTES  (SM_FLOATS * 4)

#define B_BQ  0
#define B_BL2 64
#define B_BV  128
#define B_BK  192
#define B_BW1 256
#define B_BW2 320

__device__ float g_h[NN * 64];
__device__ uint2 g_wimg[5 * 1024];   // fp16 B-frag images: Wl2, Wk, Ww1, Ww2, Wv

__device__ __forceinline__ uint32_t smem_u32(const void* p) {
    uint32_t a;
    asm("{ .reg .u64 t; cvta.to.shared.u64 t, %1; cvt.u32.u64 %0, t; }" : "=r"(a) : "l"(p));
    return a;
}
__device__ __forceinline__ uint32_t pk2h(float lo, float hi) {
    uint32_t r;
    asm("cvt.rn.f16x2.f32 %0, %1, %2;" : "=r"(r) : "f"(hi), "f"(lo));
    return r;
}
__device__ __forceinline__ void up2h(uint32_t u, float& x0, float& x1) {
    __half2 h = *(__half2*)&u;
    x0 = __low2float(h);
    x1 = __high2float(h);
}
__device__ __forceinline__ void mma16816(float* d, uint32_t a0, uint32_t a1, uint32_t a2,
                                         uint32_t a3, uint32_t b0, uint32_t b1) {
    asm volatile("mma.sync.aligned.m16n8k16.row.col.f32.f16.f16.f32 "
        "{%0,%1,%2,%3}, {%4,%5,%6,%7}, {%8,%9}, {%0,%1,%2,%3};"
        : "+f"(d[0]), "+f"(d[1]), "+f"(d[2]), "+f"(d[3])
        : "r"(a0), "r"(a1), "r"(a2), "r"(a3), "r"(b0), "r"(b1));
}
#define CP16(dst, src) asm volatile("cp.async.cg.shared.global [%0], [%1], 16;" :: "r"(dst), "l"(src) : "memory")
#define CP_COMMIT()    asm volatile("cp.async.commit_group;" ::: "memory")
#define CP_WAIT(n)     asm volatile("cp.async.wait_group %0;" :: "n"(n) : "memory")

#define PREFETCH(IMG)                                                          \
    {                                                                          \
        const uint4* src = (const uint4*)(g_wimg + (IMG) * 1024);              \
        uint32_t dst = sbase + ((IMG) & 1 ? OFF_WBUF1 : OFF_WBUF0) * 4;        \
        _Pragma("unroll")                                                      \
        for (int t = 0; t < 4; t++) CP16(dst + (tid + t * 128) * 16, src + tid + t * 128); \
        CP_COMMIT();                                                           \
    }

__device__ __forceinline__ void run_gemm(const uint2* __restrict__ Wb, int lane,
                                         const uint32_t A[2][4][4], float D[2][8][4]) {
    #pragma unroll
    for (int mt = 0; mt < 2; mt++)
        #pragma unroll
        for (int nt = 0; nt < 8; nt++)
            #pragma unroll
            for (int e = 0; e < 4; e++) D[mt][nt][e] = 0.f;
    #pragma unroll
    for (int nt = 0; nt < 8; nt++)
        #pragma unroll
        for (int kt = 0; kt < 4; kt++) {
            uint2 b = Wb[(kt * 8 + nt) * 32 + lane];
            #pragma unroll
            for (int mt = 0; mt < 2; mt++)
                mma16816(D[mt][nt], A[mt][kt][0], A[mt][kt][1], A[mt][kt][2], A[mt][kt][3], b.x, b.y);
        }
}

// pack weights into per-lane fp16 B-fragment images
__global__ void prep_kernel(const float* __restrict__ Wl2, const float* __restrict__ Wk,
                            const float* __restrict__ Ww1, const float* __restrict__ Ww2,
                            const float* __restrict__ Wv) {
    const int g = blockIdx.x;
    const float* W = (g == 0) ? Wl2 : (g == 1) ? Wk : (g == 2) ? Ww1 : (g == 3) ? Ww2 : Wv;
    for (int e = threadIdx.x; e < 1024; e += blockDim.x) {
        int lane = e & 31, tile = e >> 5;
        int kt = tile >> 3, nt = tile & 7;
        int k0 = kt * 16 + (lane & 3) * 2;
        int n = nt * 8 + (lane >> 2);
        uint2 b;
        b.x = pk2h(W[k0 * 64 + n],       W[(k0 + 1) * 64 + n]);
        b.y = pk2h(W[(k0 + 8) * 64 + n], W[(k0 + 9) * 64 + n]);
        g_wimg[g * 1024 + tile * 32 + lane] = b;
    }
}

__global__ void __launch_bounds__(128, 3)
attn_kernel(const float* __restrict__ coords, const float* __restrict__ feats,
            const float* __restrict__ Wq, const float* __restrict__ bq,
            const float* __restrict__ bk, const float* __restrict__ bv,
            const float* __restrict__ Wl1, const float* __restrict__ bl1,
            const float* __restrict__ bl2,
            const float* __restrict__ bw1, const float* __restrict__ bw2,
            const float* __restrict__ g_att, const float* __restrict__ b_att,
            const int* __restrict__ knn)
{
    extern __shared__ float sm[];
    const int tid = threadIdx.x;
    const int w = tid >> 5, lane = tid & 31;
    const int gnode = blockIdx.x * 4 + w;
    const int i0 = blockIdx.x * 4;
    const uint32_t sbase = smem_u32(sm);
    int* sIdx = (int*)(sm + OFF_IDX);

    PREFETCH(0);   // Wl2 -> WBUF0
    PREFETCH(1);   // Wk  -> WBUF1

    sIdx[w * 32 + lane] = knn[gnode * 33 + lane];
    if (lane < 3) sm[OFF_C0 + w * 4 + lane] = coords[gnode * 3 + lane];
    __syncwarp();
    {
        int j = sIdx[w * 32 + lane];
        sm[OFF_CW + (w * 32 + lane) * 3 + 0] = coords[j * 3 + 0];
        sm[OFF_CW + (w * 32 + lane) * 3 + 1] = coords[j * 3 + 1];
        sm[OFF_CW + (w * 32 + lane) * 3 + 2] = coords[j * 3 + 2];
    }
    #pragma unroll
    for (int it = 0; it < 16; it++) {   // neighbor feats tile [w][32][68]
        int r = it * 2 + (lane >> 4), c4 = lane & 15;
        int j = sIdx[w * 32 + r];
        float4 v = ((const float4*)feats)[j * 16 + c4];
        *(float4*)&sm[OFF_FW + (w * 32 + r) * 68 + c4 * 4] = v;
    }
    sm[OFF_FN + tid]       = feats[i0 * 64 + tid];
    sm[OFF_FN + tid + 128] = feats[i0 * 64 + tid + 128];
    for (int e = tid; e < 384; e += 128) {
        int s = e >> 6, c = e & 63;
        sm[OFF_BIAS + e] = (s == 0) ? bq[c] : (s == 1) ? bl2[c] : (s == 2) ? bv[c] :
                           (s == 3) ? bk[c] : (s == 4) ? bw1[c] : bw2[c];
    }
    if (tid < 128) sm[OFF_WL1 + tid] = Wl1[tid];
    if (tid < 64)  { sm[OFF_WL1 + 128 + tid] = Wl1[128 + tid]; sm[OFF_WL1 + 192 + tid] = bl1[tid]; }
    __syncthreads();

    // Q = relu(feats_node @ Wq + bq)  (exact fp32, Wq straight from gmem/L1)
    #pragma unroll
    for (int p = 0; p < 2; p++) {
        int e = tid + p * 128, n2 = e >> 6, col = e & 63;
        float acc = sm[OFF_BIAS + B_BQ + col];
        #pragma unroll 8
        for (int j = 0; j < 64; j++)
            acc = fmaf(sm[OFF_FN + n2 * 64 + j], Wq[j * 64 + col], acc);
        sm[OFF_Q + e] = fmaxf(acc, 0.f);
    }

    // hid = relu(diff @ Wl1 + bl1) -> curA frags (fp16)
    uint32_t curA[2][4][4], peA[2][4][4];
    {
        float c0x = sm[OFF_C0 + w * 4], c0y = sm[OFF_C0 + w * 4 + 1], c0z = sm[OFF_C0 + w * 4 + 2];
        float dx[4], dy[4], dz[4];
        #pragma unroll
        for (int m = 0; m < 4; m++) {
            int row = (lane >> 2) + m * 8;
            dx[m] = sm[OFF_CW + (w * 32 + row) * 3 + 0] - c0x;
            dy[m] = sm[OFF_CW + (w * 32 + row) * 3 + 1] - c0y;
            dz[m] = sm[OFF_CW + (w * 32 + row) * 3 + 2] - c0z;
        }
        #pragma unroll
        for (int kt = 0; kt < 4; kt++)
            #pragma unroll
            for (int half = 0; half < 2; half++) {
                int cc = kt * 16 + 2 * (lane & 3) + 8 * half;
                float2 w0 = *(float2*)&sm[OFF_WL1 + cc];
                float2 w1 = *(float2*)&sm[OFF_WL1 + 64 + cc];
                float2 w2 = *(float2*)&sm[OFF_WL1 + 128 + cc];
                float2 bb = *(float2*)&sm[OFF_WL1 + 192 + cc];
                #pragma unroll
                for (int mt = 0; mt < 2; mt++)
                    #pragma unroll
                    for (int rs = 0; rs < 2; rs++) {
                        int m = mt * 2 + rs;
                        float h0 = fmaxf(fmaf(dx[m], w0.x, fmaf(dy[m], w1.x, fmaf(dz[m], w2.x, bb.x))), 0.f);
                        float h1 = fmaxf(fmaf(dx[m], w0.y, fmaf(dy[m], w1.y, fmaf(dz[m], w2.y, bb.y))), 0.f);
                        curA[mt][kt][half * 2 + rs] = pk2h(h0, h1);
                    }
            }
    }
    CP_WAIT(1);        // Wl2 landed
    __syncthreads();

    float D[2][8][4];

    // ---- stage 0: fc = hid @ Wl2 ; pe = fc + bl2 + feats[j] -> peA ----
    run_gemm((const uint2*)(sm + OFF_WBUF0), lane, curA, D);
    #pragma unroll
    for (int mt = 0; mt < 2; mt++) {
        int rA = mt * 16 + (lane >> 2);
        #pragma unroll
        for (int nt = 0; nt < 8; nt++) {
            int cb = nt * 8 + 2 * (lane & 3);
            float2 b2 = *(float2*)&sm[OFF_BIAS + B_BL2 + cb];
            float2 fA = *(float2*)&sm[OFF_FW + (w * 32 + rA) * 68 + cb];
            float2 fB = *(float2*)&sm[OFF_FW + (w * 32 + rA + 8) * 68 + cb];
            peA[mt][nt >> 1][(nt & 1) * 2]     = pk2h(D[mt][nt][0] + b2.x + fA.x, D[mt][nt][1] + b2.y + fA.y);
            peA[mt][nt >> 1][(nt & 1) * 2 + 1] = pk2h(D[mt][nt][2] + b2.x + fB.x, D[mt][nt][3] + b2.y + fB.y);
        }
    }
    __syncthreads();
    PREFETCH(2);   // Ww1 -> WBUF0
    CP_WAIT(1);
    __syncthreads();

    // ---- stage 1: Kf = pe @ Wk ; rel = (relu(Kf+bk) - Q) * (pe - feats[j]) -> curA ----
    run_gemm((const uint2*)(sm + OFF_WBUF1), lane, peA, D);
    #pragma unroll
    for (int mt = 0; mt < 2; mt++) {
        int rA = mt * 16 + (lane >> 2);
        #pragma unroll
        for (int nt = 0; nt < 8; nt++) {
            int cb = nt * 8 + 2 * (lane & 3);
            float2 b2 = *(float2*)&sm[OFF_BIAS + B_BK + cb];
            float2 q2 = *(float2*)&sm[OFF_Q + w * 64 + cb];
            float2 fA = *(float2*)&sm[OFF_FW + (w * 32 + rA) * 68 + cb];
            float2 fB = *(float2*)&sm[OFF_FW + (w * 32 + rA + 8) * 68 + cb];
            float pe0, pe1, pe2, pe3;
            up2h(peA[mt][nt >> 1][(nt & 1) * 2],     pe0, pe1);
            up2h(peA[mt][nt >> 1][(nt & 1) * 2 + 1], pe2, pe3);
            float r0 = (fmaxf(D[mt][nt][0] + b2.x, 0.f) - q2.x) * (pe0 - fA.x);
            float r1 = (fmaxf(D[mt][nt][1] + b2.y, 0.f) - q2.y) * (pe1 - fA.y);
            float r2 = (fmaxf(D[mt][nt][2] + b2.x, 0.f) - q2.x) * (pe2 - fB.x);
            float r3 = (fmaxf(D[mt][nt][3] + b2.y, 0.f) - q2.y) * (pe3 - fB.y);
            curA[mt][nt >> 1][(nt & 1) * 2]     = pk2h(r0, r1);
            curA[mt][nt >> 1][(nt & 1) * 2 + 1] = pk2h(r2, r3);
        }
    }
    __syncthreads();
    PREFETCH(3);   // Ww2 -> WBUF1
    CP_WAIT(1);
    __syncthreads();

    // ---- stage 2: wh = relu(rel @ Ww1 + bw1) -> curA ----
    run_gemm((const uint2*)(sm + OFF_WBUF0), lane, curA, D);
    #pragma unroll
    for (int mt = 0; mt < 2; mt++)
        #pragma unroll
        for (int nt = 0; nt < 8; nt++) {
            int cb = nt * 8 + 2 * (lane & 3);
            float2 b2 = *(float2*)&sm[OFF_BIAS + B_BW1 + cb];
            curA[mt][nt >> 1][(nt & 1) * 2]     = pk2h(fmaxf(D[mt][nt][0] + b2.x, 0.f),
                                                       fmaxf(D[mt][nt][1] + b2.y, 0.f));
            curA[mt][nt >> 1][(nt & 1) * 2 + 1] = pk2h(fmaxf(D[mt][nt][2] + b2.x, 0.f),
                                                       fmaxf(D[mt][nt][3] + b2.y, 0.f));
        }
    __syncthreads();
    PREFETCH(4);   // Wv -> WBUF0
    CP_WAIT(1);
    __syncthreads();

    // ---- stage 3: z = wh @ Ww2 + bw2 -> zT smem (overwrites feats tile) ----
    run_gemm((const uint2*)(sm + OFF_WBUF1), lane, curA, D);
    __syncthreads();   // all FW feats reads done before overwrite
    #pragma unroll
    for (int mt = 0; mt < 2; mt++) {
        int rA = mt * 16 + (lane >> 2);
        #pragma unroll
        for (int nt = 0; nt < 8; nt++) {
            int cb = nt * 8 + 2 * (lane & 3);
            float2 b2 = *(float2*)&sm[OFF_BIAS + B_BW2 + cb];
            sm[OFF_FW + (w * 64 + cb)     * 36 + rA]     = D[mt][nt][0] + b2.x;
            sm[OFF_FW + (w * 64 + cb + 1) * 36 + rA]     = D[mt][nt][1] + b2.y;
            sm[OFF_FW + (w * 64 + cb)     * 36 + rA + 8] = D[mt][nt][2] + b2.x;
            sm[OFF_FW + (w * 64 + cb + 1) * 36 + rA + 8] = D[mt][nt][3] + b2.y;
        }
    }
    __syncthreads();

    // ---- sparsemax (Michelot fixed point): tau per (node,col) ----
    #pragma unroll
    for (int p = 0; p < 2; p++) {
        int q = tid + p * 128;
        float z[32];
        const float* zp = &sm[OFF_FW + q * 36];
        #pragma unroll
        for (int j = 0; j < 8; j++) {
            float4 v = *(const float4*)&zp[j * 4];
            z[4 * j] = v.x; z[4 * j + 1] = v.y; z[4 * j + 2] = v.z; z[4 * j + 3] = v.w;
        }
        float s = 0.f;
        #pragma unroll
        for (int k = 0; k < 32; k++) s += z[k];
        float cnt = 32.f, tau = (s - 1.f) / cnt;
        for (int it = 0; it < 32; it++) {
            float ns = 0.f, nc = 0.f;
            #pragma unroll
            for (int k = 0; k < 32; k++)
                if (z[k] > tau) { ns += z[k]; nc += 1.f; }
            if (nc == cnt) break;
            cnt = nc; tau = (ns - 1.f) / nc;
        }
        sm[OFF_Q + q] = tau;   // Q region reused for tau
    }
    __syncthreads();
    CP_WAIT(0);   // Wv landed

    // ---- stage 4: V = pe @ Wv + bv ; attn = sum_k relu(z - tau)*V ; LN ----
    run_gemm((const uint2*)(sm + OFF_WBUF0), lane, peA, D);
    float part[16];
    #pragma unroll
    for (int j = 0; j < 16; j++) part[j] = 0.f;
    #pragma unroll
    for (int mt = 0; mt < 2; mt++) {
        int rA = mt * 16 + (lane >> 2);
        #pragma unroll
        for (int nt = 0; nt < 8; nt++) {
            int cb = nt * 8 + 2 * (lane & 3);
            float2 b2 = *(float2*)&sm[OFF_BIAS + B_BV + cb];
            float2 t2 = *(float2*)&sm[OFF_Q + w * 64 + cb];
            #pragma unroll
            for (int rs = 0; rs < 2; rs++) {
                int row = rA + rs * 8;
                float z0 = sm[OFF_FW + (w * 64 + cb)     * 36 + row];
                float z1 = sm[OFF_FW + (w * 64 + cb + 1) * 36 + row];
                part[nt * 2]     = fmaf(fmaxf(z0 - t2.x, 0.f), D[mt][nt][rs * 2]     + b2.x, part[nt * 2]);
                part[nt * 2 + 1] = fmaf(fmaxf(z1 - t2.y, 0.f), D[mt][nt][rs * 2 + 1] + b2.y, part[nt * 2 + 1]);
            }
        }
    }
    #pragma unroll
    for (int j = 0; j < 16; j++) {
        float v = part[j];
        v += __shfl_xor_sync(0xffffffffu, v, 4);
        v += __shfl_xor_sync(0xffffffffu, v, 8);
        v += __shfl_xor_sync(0xffffffffu, v, 16);
        part[j] = v;
    }
    float xs[16], tot = 0.f;
    #pragma unroll
    for (int j = 0; j < 16; j++) {
        int col = 8 * (j >> 1) + 2 * (lane & 3) + (j & 1);
        xs[j] = fmaf(2.f, sm[OFF_FN + w * 64 + col], part[j]);
        tot += xs[j];
    }
    #pragma unroll
    for (int off = 16; off > 0; off >>= 1) tot += __shfl_xor_sync(0xffffffffu, tot, off);
    const float mean = tot * (1.f / 512.f);
    float vt = 0.f;
    #pragma unroll
    for (int j = 0; j < 16; j++) { float c = xs[j] - mean; vt += c * c; }
    #pragma unroll
    for (int off = 16; off > 0; off >>= 1) vt += __shfl_xor_sync(0xffffffffu, vt, off);
    const float rsg = rsqrtf(vt * (1.f / 512.f) + 1e-5f);
    if ((lane >> 2) == 0) {
        #pragma unroll
        for (int j = 0; j < 16; j++) {
            int col = 8 * (j >> 1) + 2 * (lane & 3) + (j & 1);
            g_h[gnode * 64 + col] = fmaf(g_att[col] * (xs[j] - mean), rsg, b_att[col]);
        }
    }
}

// ---------------- GCN + FF + LN : 4 nodes per 64-thread block ----------------
__global__ __launch_bounds__(64, 16)
void gcn_kernel(const float* __restrict__ coords,
                const float* __restrict__ Wsg, const float* __restrict__ bsg,
                const float* __restrict__ Wf,  const float* __restrict__ bf,
                const float* __restrict__ g_ff, const float* __restrict__ b_ff,
                const int* __restrict__ knn,
                float* __restrict__ out)
{
    const int i0 = blockIdx.x * 4;
    const int d = threadIdx.x;
    const int wid = d >> 5, lane = d & 31;

    __shared__ int   sIdx[4][32];
    __shared__ float sAgg[4][68];
    __shared__ float s1[4][64];
    __shared__ float red[4][2];

    #pragma unroll
    for (int t = 0; t < 2; t++) {
        int e = d + t * 64;
        sIdx[e >> 5][e & 31] = knn[(i0 + (e >> 5)) * 33 + 1 + (e & 31)];
    }
    __syncthreads();

    float hd[4], a[4];
    #pragma unroll
    for (int n = 0; n < 4; n++) { hd[n] = g_h[(i0 + n) * 64 + d]; a[n] = hd[n]; }
    #pragma unroll 4
    for (int k = 0; k < 32; k++) {
        #pragma unroll
        for (int n = 0; n < 4; n++) a[n] += g_h[sIdx[n][k] * 64 + d];
    }
    #pragma unroll
    for (int n = 0; n < 4; n++) sAgg[n][d] = a[n] * (1.f / 33.f);
    if (d < 12) {
        int n = d / 3, c = d - n * 3;
        float cc = coords[(i0 + n) * 3 + c];
        for (int k = 0; k < 32; k++) cc += coords[sIdx[n][k] * 3 + c];
        sAgg[n][64 + c] = cc * (1.f / 33.f);
    }
    __syncthreads();

    float x1[4];
    {
        float bb = bsg[d];
        #pragma unroll
        for (int n = 0; n < 4; n++) x1[n] = bb;
    }
    #pragma unroll 4
    for (int j = 0; j < 67; j++) {
        float ww = Wsg[j * 64 + d];
        #pragma unroll
        for (int n = 0; n < 4; n++) x1[n] = fmaf(sAgg[n][j], ww, x1[n]);
    }
    #pragma unroll
    for (int n = 0; n < 4; n++) s1[n][d] = fmaxf(x1[n], 0.f);
    __syncthreads();

    float x[4];
    {
        float bb = bf[d];
        #pragma unroll
        for (int n = 0; n < 4; n++) x[n] = bb;
    }
    #pragma unroll 4
    for (int j = 0; j < 64; j++) {
        float ww = Wf[j * 64 + d];
        #pragma unroll
        for (int n = 0; n < 4; n++) x[n] = fmaf(s1[n][j], ww, x[n]);
    }
    #pragma unroll
    for (int n = 0; n < 4; n++) x[n] += hd[n];

    // LayerNorm per node (64 values over 2 warps)
    #pragma unroll
    for (int n = 0; n < 4; n++) {
        float r = x[n];
        #pragma unroll
        for (int off = 16; off > 0; off >>= 1) r += __shfl_xor_sync(0xffffffffu, r, off);
        if (lane == 0) red[n][wid] = r;
    }
    __syncthreads();
    float mean[4], cv[4];
    #pragma unroll
    for (int n = 0; n < 4; n++) {
        mean[n] = (red[n][0] + red[n][1]) * (1.f / 64.f);
        cv[n] = x[n] - mean[n];
    }
    __syncthreads();
    #pragma unroll
    for (int n = 0; n < 4; n++) {
        float r = cv[n] * cv[n];
        #pragma unroll
        for (int off = 16; off > 0; off >>= 1) r += __shfl_xor_sync(0xffffffffu, r, off);
        if (lane == 0) red[n][wid] = r;
    }
    __syncthreads();
    const float gd = g_ff[d], bd = b_ff[d];
    #pragma unroll
    for (int n = 0; n < 4; n++) {
        float var = (red[n][0] + red[n][1]) * (1.f / 64.f);
        out[(i0 + n) * 64 + d] = fmaf(gd * cv[n], rsqrtf(var + 1e-5f), bd);
    }
}

extern "C" void kernel_launch(void* const* d_in, const int* in_sizes, int n_in,
                              void* d_out, int out_size)
{
    const float* coords = (const float*)d_in[0];
    const float* feats  = (const float*)d_in[1];
    const float* Wq  = (const float*)d_in[2];
    const float* bq  = (const float*)d_in[3];
    const float* Wk  = (const float*)d_in[4];
    const float* bk  = (const float*)d_in[5];
    const float* Wv  = (const float*)d_in[6];
    const float* bv  = (const float*)d_in[7];
    const float* Wl1 = (const float*)d_in[8];
    const float* bl1 = (const float*)d_in[9];
    const float* Wl2 = (const float*)d_in[10];
    const float* bl2 = (const float*)d_in[11];
    const float* Ww1 = (const float*)d_in[12];
    const float* bw1 = (const float*)d_in[13];
    const float* Ww2 = (const float*)d_in[14];
    const float* bw2 = (const float*)d_in[15];
    const float* g_att = (const float*)d_in[16];
    const float* b_att = (const float*)d_in[17];
    const float* Wsg = (const float*)d_in[18];
    const float* bsg = (const float*)d_in[19];
    const float* Wf  = (const float*)d_in[20];
    const float* bf  = (const float*)d_in[21];
    const float* g_ff = (const float*)d_in[22];
    const float* b_ff = (const float*)d_in[23];
    const int*   knn  = (const int*)d_in[24];

    cudaFuncSetAttribute(attn_kernel, cudaFuncAttributeMaxDynamicSharedMemorySize, SM_BYTES);

    prep_kernel<<<5, 256>>>(Wl2, Wk, Ww1, Ww2, Wv);
    attn_kernel<<<NN / 4, 128, SM_BYTES>>>(coords, feats, Wq, bq, bk, bv,
                                           Wl1, bl1, bl2, bw1, bw2,
                                           g_att, b_att, knn);
    gcn_kernel<<<NN / 4, 64>>>(coords, Wsg, bsg, Wf, bf, g_ff, b_ff, knn,
                               (float*)d_out);
}

// round 8
// speedup vs baseline: 4.7316x; 1.0922x over previous
#include <cuda_runtime.h>
#include <cuda_fp16.h>
#include <cstdint>

#define NN 20000
// smem float offsets
#define OFF_WBUF0 0        /* 2048 floats (8KB) */
#define OFF_WBUF1 2048     /* 2048 */
#define OFF_FW    4096     /* feats [4][32][68]=8704 ; later zT [256][34]=8704 */
#define OFF_FN    12800    /* 256 */
#define OFF_Q     13056    /* 256 (Q, later tau) */
#define OFF_BIAS  13312    /* 384 */
#define OFF_WL1   13696    /* 256 */
#define OFF_C0    13952    /* 16 */
#define OFF_IDX   13968    /* 128 ints */
#define SM_FLOATS 14096
#define SM_BYTES  (SM_FLOATS * 4)

#define B_BQ  0
#define B_BL2 64
#define B_BV  128
#define B_BK  192
#define B_BW1 256
#define B_BW2 320

#define ZSTR 34

__device__ float g_h[NN * 64];
__device__ uint2 g_wimg[5 * 1024];   // fp16 B-frag images: Wl2, Wk, Ww1, Ww2, Wv

__device__ __forceinline__ uint32_t smem_u32(const void* p) {
    uint32_t a;
    asm("{ .reg .u64 t; cvta.to.shared.u64 t, %1; cvt.u32.u64 %0, t; }" : "=r"(a) : "l"(p));
    return a;
}
__device__ __forceinline__ uint32_t pk2h(float lo, float hi) {
    uint32_t r;
    asm("cvt.rn.f16x2.f32 %0, %1, %2;" : "=r"(r) : "f"(hi), "f"(lo));
    return r;
}
__device__ __forceinline__ void up2h(uint32_t u, float& x0, float& x1) {
    __half2 h = *(__half2*)&u;
    x0 = __low2float(h);
    x1 = __high2float(h);
}
__device__ __forceinline__ void mma16816(float* d, uint32_t a0, uint32_t a1, uint32_t a2,
                                         uint32_t a3, uint32_t b0, uint32_t b1) {
    asm volatile("mma.sync.aligned.m16n8k16.row.col.f32.f16.f16.f32 "
        "{%0,%1,%2,%3}, {%4,%5,%6,%7}, {%8,%9}, {%0,%1,%2,%3};"
        : "+f"(d[0]), "+f"(d[1]), "+f"(d[2]), "+f"(d[3])
        : "r"(a0), "r"(a1), "r"(a2), "r"(a3), "r"(b0), "r"(b1));
}
#define CP16(dst, src) asm volatile("cp.async.cg.shared.global [%0], [%1], 16;" :: "r"(dst), "l"(src) : "memory")
#define CP_COMMIT()    asm volatile("cp.async.commit_group;" ::: "memory")
#define CP_WAIT(n)     asm volatile("cp.async.wait_group %0;" :: "n"(n) : "memory")

#define PREFETCH(IMG)                                                          \
    {                                                                          \
        const uint4* src = (const uint4*)(g_wimg + (IMG) * 1024);              \
        uint32_t dst = sbase + ((IMG) & 1 ? OFF_WBUF1 : OFF_WBUF0) * 4;        \
        _Pragma("unroll")                                                      \
        for (int t = 0; t < 4; t++) CP16(dst + (tid + t * 128) * 16, src + tid + t * 128); \
        CP_COMMIT();                                                           \
    }

// half-GEMM: one mt tile (16 rows), D[8][4] = A1[16x64] @ W[64x64]
__device__ __forceinline__ void run_gemm_half(const uint2* __restrict__ Wb, int lane,
                                              const uint32_t A1[4][4], float D[8][4]) {
    #pragma unroll
    for (int nt = 0; nt < 8; nt++)
        #pragma unroll
        for (int e = 0; e < 4; e++) D[nt][e] = 0.f;
    #pragma unroll
    for (int nt = 0; nt < 8; nt++)
        #pragma unroll
        for (int kt = 0; kt < 4; kt++) {
            uint2 b = Wb[(kt * 8 + nt) * 32 + lane];
            mma16816(D[nt], A1[kt][0], A1[kt][1], A1[kt][2], A1[kt][3], b.x, b.y);
        }
}

// pack weights into per-lane fp16 B-fragment images
__global__ void prep_kernel(const float* __restrict__ Wl2, const float* __restrict__ Wk,
                            const float* __restrict__ Ww1, const float* __restrict__ Ww2,
                            const float* __restrict__ Wv) {
    const int g = blockIdx.x;
    const float* W = (g == 0) ? Wl2 : (g == 1) ? Wk : (g == 2) ? Ww1 : (g == 3) ? Ww2 : Wv;
    for (int e = threadIdx.x; e < 1024; e += blockDim.x) {
        int lane = e & 31, tile = e >> 5;
        int kt = tile >> 3, nt = tile & 7;
        int k0 = kt * 16 + (lane & 3) * 2;
        int n = nt * 8 + (lane >> 2);
        uint2 b;
        b.x = pk2h(W[k0 * 64 + n],       W[(k0 + 1) * 64 + n]);
        b.y = pk2h(W[(k0 + 8) * 64 + n], W[(k0 + 9) * 64 + n]);
        g_wimg[g * 1024 + tile * 32 + lane] = b;
    }
}

__global__ void __launch_bounds__(128, 4)
attn_kernel(const float* __restrict__ coords, const float* __restrict__ feats,
            const float* __restrict__ Wq, const float* __restrict__ bq,
            const float* __restrict__ bk, const float* __restrict__ bv,
            const float* __restrict__ Wl1, const float* __restrict__ bl1,
            const float* __restrict__ bl2,
            const float* __restrict__ bw1, const float* __restrict__ bw2,
            const float* __restrict__ g_att, const float* __restrict__ b_att,
            const int* __restrict__ knn)
{
    extern __shared__ float sm[];
    const int tid = threadIdx.x;
    const int w = tid >> 5, lane = tid & 31;
    const int gnode = blockIdx.x * 4 + w;
    const int i0 = blockIdx.x * 4;
    const uint32_t sbase = smem_u32(sm);
    int* sIdx = (int*)(sm + OFF_IDX);

    PREFETCH(0);   // Wl2 -> WBUF0
    PREFETCH(1);   // Wk  -> WBUF1

    const int jn = knn[gnode * 33 + lane];
    sIdx[w * 32 + lane] = jn;
    if (lane < 3) sm[OFF_C0 + w * 4 + lane] = coords[gnode * 3 + lane];
    // this lane's neighbor coords (registers; rows fetched via shuffle)
    const float ncx = coords[jn * 3 + 0];
    const float ncy = coords[jn * 3 + 1];
    const float ncz = coords[jn * 3 + 2];
    __syncwarp();
    #pragma unroll
    for (int it = 0; it < 16; it++) {   // neighbor feats tile [w][32][68]
        int r = it * 2 + (lane >> 4), c4 = lane & 15;
        int j = sIdx[w * 32 + r];
        float4 v = ((const float4*)feats)[j * 16 + c4];
        *(float4*)&sm[OFF_FW + (w * 32 + r) * 68 + c4 * 4] = v;
    }
    sm[OFF_FN + tid]       = feats[i0 * 64 + tid];
    sm[OFF_FN + tid + 128] = feats[i0 * 64 + tid + 128];
    for (int e = tid; e < 384; e += 128) {
        int s = e >> 6, c = e & 63;
        sm[OFF_BIAS + e] = (s == 0) ? bq[c] : (s == 1) ? bl2[c] : (s == 2) ? bv[c] :
                           (s == 3) ? bk[c] : (s == 4) ? bw1[c] : bw2[c];
    }
    if (tid < 128) sm[OFF_WL1 + tid] = Wl1[tid];
    if (tid < 64)  { sm[OFF_WL1 + 128 + tid] = Wl1[128 + tid]; sm[OFF_WL1 + 192 + tid] = bl1[tid]; }
    __syncthreads();

    // Q = relu(feats_node @ Wq + bq): one (node, col-pair) per thread, float2
    {
        const int n2 = tid >> 5, cp = (tid & 31) * 2;
        float2 acc = *(float2*)&sm[OFF_BIAS + B_BQ + cp];
        #pragma unroll 8
        for (int j = 0; j < 64; j++) {
            float f = sm[OFF_FN + n2 * 64 + j];
            float2 w2 = *(const float2*)&Wq[j * 64 + cp];
            acc.x = fmaf(f, w2.x, acc.x);
            acc.y = fmaf(f, w2.y, acc.y);
        }
        sm[OFF_Q + n2 * 64 + cp]     = fmaxf(acc.x, 0.f);
        sm[OFF_Q + n2 * 64 + cp + 1] = fmaxf(acc.y, 0.f);
    }

    // hid = relu(diff @ Wl1 + bl1) -> curA frags (fp16)
    uint32_t curA[2][4][4], peA[2][4][4];
    {
        float c0x = sm[OFF_C0 + w * 4], c0y = sm[OFF_C0 + w * 4 + 1], c0z = sm[OFF_C0 + w * 4 + 2];
        float dx[4], dy[4], dz[4];
        #pragma unroll
        for (int m = 0; m < 4; m++) {
            int row = (lane >> 2) + m * 8;
            dx[m] = __shfl_sync(0xffffffffu, ncx, row) - c0x;
            dy[m] = __shfl_sync(0xffffffffu, ncy, row) - c0y;
            dz[m] = __shfl_sync(0xffffffffu, ncz, row) - c0z;
        }
        #pragma unroll
        for (int kt = 0; kt < 4; kt++)
            #pragma unroll
            for (int half = 0; half < 2; half++) {
                int cc = kt * 16 + 2 * (lane & 3) + 8 * half;
                float2 w0 = *(float2*)&sm[OFF_WL1 + cc];
                float2 w1 = *(float2*)&sm[OFF_WL1 + 64 + cc];
                float2 w2 = *(float2*)&sm[OFF_WL1 + 128 + cc];
                float2 bb = *(float2*)&sm[OFF_WL1 + 192 + cc];
                #pragma unroll
                for (int mt = 0; mt < 2; mt++)
                    #pragma unroll
                    for (int rs = 0; rs < 2; rs++) {
                        int m = mt * 2 + rs;
                        float h0 = fmaxf(fmaf(dx[m], w0.x, fmaf(dy[m], w1.x, fmaf(dz[m], w2.x, bb.x))), 0.f);
                        float h1 = fmaxf(fmaf(dx[m], w0.y, fmaf(dy[m], w1.y, fmaf(dz[m], w2.y, bb.y))), 0.f);
                        curA[mt][kt][half * 2 + rs] = pk2h(h0, h1);
                    }
            }
    }
    CP_WAIT(1);        // Wl2 landed
    __syncthreads();

    float D[8][4];

    // ---- stage 0: fc = hid @ Wl2 ; pe = fc + bl2 + feats[j] -> peA ----
    #pragma unroll
    for (int mt = 0; mt < 2; mt++) {
        run_gemm_half((const uint2*)(sm + OFF_WBUF0), lane, curA[mt], D);
        int rA = mt * 16 + (lane >> 2);
        #pragma unroll
        for (int nt = 0; nt < 8; nt++) {
            int cb = nt * 8 + 2 * (lane & 3);
            float2 b2 = *(float2*)&sm[OFF_BIAS + B_BL2 + cb];
            float2 fA = *(float2*)&sm[OFF_FW + (w * 32 + rA) * 68 + cb];
            float2 fB = *(float2*)&sm[OFF_FW + (w * 32 + rA + 8) * 68 + cb];
            peA[mt][nt >> 1][(nt & 1) * 2]     = pk2h(D[nt][0] + b2.x + fA.x, D[nt][1] + b2.y + fA.y);
            peA[mt][nt >> 1][(nt & 1) * 2 + 1] = pk2h(D[nt][2] + b2.x + fB.x, D[nt][3] + b2.y + fB.y);
        }
    }
    __syncthreads();
    PREFETCH(2);   // Ww1 -> WBUF0
    CP_WAIT(1);
    __syncthreads();

    // ---- stage 1: Kf = pe @ Wk ; rel = (relu(Kf+bk) - Q) * (pe - feats[j]) -> curA ----
    #pragma unroll
    for (int mt = 0; mt < 2; mt++) {
        run_gemm_half((const uint2*)(sm + OFF_WBUF1), lane, peA[mt], D);
        int rA = mt * 16 + (lane >> 2);
        #pragma unroll
        for (int nt = 0; nt < 8; nt++) {
            int cb = nt * 8 + 2 * (lane & 3);
            float2 b2 = *(float2*)&sm[OFF_BIAS + B_BK + cb];
            float2 q2 = *(float2*)&sm[OFF_Q + w * 64 + cb];
            float2 fA = *(float2*)&sm[OFF_FW + (w * 32 + rA) * 68 + cb];
            float2 fB = *(float2*)&sm[OFF_FW + (w * 32 + rA + 8) * 68 + cb];
            float pe0, pe1, pe2, pe3;
            up2h(peA[mt][nt >> 1][(nt & 1) * 2],     pe0, pe1);
            up2h(peA[mt][nt >> 1][(nt & 1) * 2 + 1], pe2, pe3);
            float r0 = (fmaxf(D[nt][0] + b2.x, 0.f) - q2.x) * (pe0 - fA.x);
            float r1 = (fmaxf(D[nt][1] + b2.y, 0.f) - q2.y) * (pe1 - fA.y);
            float r2 = (fmaxf(D[nt][2] + b2.x, 0.f) - q2.x) * (pe2 - fB.x);
            float r3 = (fmaxf(D[nt][3] + b2.y, 0.f) - q2.y) * (pe3 - fB.y);
            curA[mt][nt >> 1][(nt & 1) * 2]     = pk2h(r0, r1);
            curA[mt][nt >> 1][(nt & 1) * 2 + 1] = pk2h(r2, r3);
        }
    }
    __syncthreads();
    PREFETCH(3);   // Ww2 -> WBUF1
    CP_WAIT(1);
    __syncthreads();

    // ---- stage 2: wh = relu(rel @ Ww1 + bw1) -> curA ----
    #pragma unroll
    for (int mt = 0; mt < 2; mt++) {
        run_gemm_half((const uint2*)(sm + OFF_WBUF0), lane, curA[mt], D);
        #pragma unroll
        for (int nt = 0; nt < 8; nt++) {
            int cb = nt * 8 + 2 * (lane & 3);
            float2 b2 = *(float2*)&sm[OFF_BIAS + B_BW1 + cb];
            curA[mt][nt >> 1][(nt & 1) * 2]     = pk2h(fmaxf(D[nt][0] + b2.x, 0.f),
                                                       fmaxf(D[nt][1] + b2.y, 0.f));
            curA[mt][nt >> 1][(nt & 1) * 2 + 1] = pk2h(fmaxf(D[nt][2] + b2.x, 0.f),
                                                       fmaxf(D[nt][3] + b2.y, 0.f));
        }
    }
    __syncthreads();   // feats tile reads fully done (stage1) across CTA
    PREFETCH(4);   // Wv -> WBUF0
    CP_WAIT(1);
    __syncthreads();

    // ---- stage 3: z = wh @ Ww2 + bw2 -> zT smem (overwrites feats tile) ----
    #pragma unroll
    for (int mt = 0; mt < 2; mt++) {
        run_gemm_half((const uint2*)(sm + OFF_WBUF1), lane, curA[mt], D);
        int rA = mt * 16 + (lane >> 2);
        #pragma unroll
        for (int nt = 0; nt < 8; nt++) {
            int cb = nt * 8 + 2 * (lane & 3);
            float2 b2 = *(float2*)&sm[OFF_BIAS + B_BW2 + cb];
            sm[OFF_FW + (w * 64 + cb)     * ZSTR + rA]     = D[nt][0] + b2.x;
            sm[OFF_FW + (w * 64 + cb + 1) * ZSTR + rA]     = D[nt][1] + b2.y;
            sm[OFF_FW + (w * 64 + cb)     * ZSTR + rA + 8] = D[nt][2] + b2.x;
            sm[OFF_FW + (w * 64 + cb + 1) * ZSTR + rA + 8] = D[nt][3] + b2.y;
        }
    }
    __syncthreads();

    // ---- sparsemax (Michelot fixed point): tau per (node,col) ----
    #pragma unroll
    for (int p = 0; p < 2; p++) {
        int q = tid + p * 128;
        float z[32];
        const float* zp = &sm[OFF_FW + q * ZSTR];
        #pragma unroll
        for (int j = 0; j < 16; j++) {
            float2 v = *(const float2*)&zp[j * 2];
            z[2 * j] = v.x; z[2 * j + 1] = v.y;
        }
        float s = 0.f;
        #pragma unroll
        for (int k = 0; k < 32; k++) s += z[k];
        float cnt = 32.f, tau = (s - 1.f) / cnt;
        for (int it = 0; it < 32; it++) {
            float ns = 0.f, nc = 0.f;
            #pragma unroll
            for (int k = 0; k < 32; k++)
                if (z[k] > tau) { ns += z[k]; nc += 1.f; }
            if (nc == cnt) break;
            cnt = nc; tau = (ns - 1.f) / nc;
        }
        sm[OFF_Q + q] = tau;   // Q region reused for tau
    }
    __syncthreads();
    CP_WAIT(0);   // Wv landed

    // ---- stage 4: V = pe @ Wv + bv ; attn = sum_k relu(z - tau)*V ; LN ----
    float part[16];
    #pragma unroll
    for (int j = 0; j < 16; j++) part[j] = 0.f;
    #pragma unroll
    for (int mt = 0; mt < 2; mt++) {
        run_gemm_half((const uint2*)(sm + OFF_WBUF0), lane, peA[mt], D);
        int rA = mt * 16 + (lane >> 2);
        #pragma unroll
        for (int nt = 0; nt < 8; nt++) {
            int cb = nt * 8 + 2 * (lane & 3);
            float2 b2 = *(float2*)&sm[OFF_BIAS + B_BV + cb];
            float2 t2 = *(float2*)&sm[OFF_Q + w * 64 + cb];
            #pragma unroll
            for (int rs = 0; rs < 2; rs++) {
                int row = rA + rs * 8;
                float z0 = sm[OFF_FW + (w * 64 + cb)     * ZSTR + row];
                float z1 = sm[OFF_FW + (w * 64 + cb + 1) * ZSTR + row];
                part[nt * 2]     = fmaf(fmaxf(z0 - t2.x, 0.f), D[nt][rs * 2]     + b2.x, part[nt * 2]);
                part[nt * 2 + 1] = fmaf(fmaxf(z1 - t2.y, 0.f), D[nt][rs * 2 + 1] + b2.y, part[nt * 2 + 1]);
            }
        }
    }
    #pragma unroll
    for (int j = 0; j < 16; j++) {
        float v = part[j];
        v += __shfl_xor_sync(0xffffffffu, v, 4);
        v += __shfl_xor_sync(0xffffffffu, v, 8);
        v += __shfl_xor_sync(0xffffffffu, v, 16);
        part[j] = v;
    }
    float xs[16], tot = 0.f;
    #pragma unroll
    for (int j = 0; j < 16; j++) {
        int col = 8 * (j >> 1) + 2 * (lane & 3) + (j & 1);
        xs[j] = fmaf(2.f, sm[OFF_FN + w * 64 + col], part[j]);
        tot += xs[j];
    }
    #pragma unroll
    for (int off = 16; off > 0; off >>= 1) tot += __shfl_xor_sync(0xffffffffu, tot, off);
    const float mean = tot * (1.f / 512.f);
    float vt = 0.f;
    #pragma unroll
    for (int j = 0; j < 16; j++) { float c = xs[j] - mean; vt += c * c; }
    #pragma unroll
    for (int off = 16; off > 0; off >>= 1) vt += __shfl_xor_sync(0xffffffffu, vt, off);
    const float rsg = rsqrtf(vt * (1.f / 512.f) + 1e-5f);
    if ((lane >> 2) == 0) {
        #pragma unroll
        for (int j = 0; j < 16; j++) {
            int col = 8 * (j >> 1) + 2 * (lane & 3) + (j & 1);
            g_h[gnode * 64 + col] = fmaf(g_att[col] * (xs[j] - mean), rsg, b_att[col]);
        }
    }
}

// ---------------- GCN + FF + LN : 8 nodes per 64-thread block ----------------
__global__ __launch_bounds__(64, 16)
void gcn_kernel(const float* __restrict__ coords,
                const float* __restrict__ Wsg, const float* __restrict__ bsg,
                const float* __restrict__ Wf,  const float* __restrict__ bf,
                const float* __restrict__ g_ff, const float* __restrict__ b_ff,
                const int* __restrict__ knn,
                float* __restrict__ out)
{
    const int i0 = blockIdx.x * 8;
    const int d = threadIdx.x;
    const int wid = d >> 5, lane = d & 31;

    __shared__ int   sIdx[8][32];
    __shared__ float sAgg[8][68];
    __shared__ float s1[8][64];
    __shared__ float red[8][2];

    #pragma unroll
    for (int t = 0; t < 4; t++) {
        int e = d + t * 64;
        sIdx[e >> 5][e & 31] = knn[(i0 + (e >> 5)) * 33 + 1 + (e & 31)];
    }
    __syncthreads();

    float hd[8], a[8];
    #pragma unroll
    for (int n = 0; n < 8; n++) { hd[n] = g_h[(i0 + n) * 64 + d]; a[n] = hd[n]; }
    #pragma unroll 4
    for (int k = 0; k < 32; k++) {
        #pragma unroll
        for (int n = 0; n < 8; n++) a[n] += g_h[sIdx[n][k] * 64 + d];
    }
    #pragma unroll
    for (int n = 0; n < 8; n++) sAgg[n][d] = a[n] * (1.f / 33.f);
    if (d < 24) {
        int n = d / 3, c = d - n * 3;
        float cc = coords[(i0 + n) * 3 + c];
        for (int k = 0; k < 32; k++) cc += coords[sIdx[n][k] * 3 + c];
        sAgg[n][64 + c] = cc * (1.f / 33.f);
    }
    __syncthreads();

    float x1[8];
    {
        float bb = bsg[d];
        #pragma unroll
        for (int n = 0; n < 8; n++) x1[n] = bb;
    }
    #pragma unroll 4
    for (int j = 0; j < 67; j++) {
        float ww = Wsg[j * 64 + d];
        #pragma unroll
        for (int n = 0; n < 8; n++) x1[n] = fmaf(sAgg[n][j], ww, x1[n]);
    }
    #pragma unroll
    for (int n = 0; n < 8; n++) s1[n][d] = fmaxf(x1[n], 0.f);
    __syncthreads();

    float x[8];
    {
        float bb = bf[d];
        #pragma unroll
        for (int n = 0; n < 8; n++) x[n] = bb;
    }
    #pragma unroll 4
    for (int j = 0; j < 64; j++) {
        float ww = Wf[j * 64 + d];
        #pragma unroll
        for (int n = 0; n < 8; n++) x[n] = fmaf(s1[n][j], ww, x[n]);
    }
    #pragma unroll
    for (int n = 0; n < 8; n++) x[n] += hd[n];

    // LayerNorm per node (64 values over 2 warps)
    #pragma unroll
    for (int n = 0; n < 8; n++) {
        float r = x[n];
        #pragma unroll
        for (int off = 16; off > 0; off >>= 1) r += __shfl_xor_sync(0xffffffffu, r, off);
        if (lane == 0) red[n][wid] = r;
    }
    __syncthreads();
    float cv[8];
    #pragma unroll
    for (int n = 0; n < 8; n++)
        cv[n] = x[n] - (red[n][0] + red[n][1]) * (1.f / 64.f);
    __syncthreads();
    #pragma unroll
    for (int n = 0; n < 8; n++) {
        float r = cv[n] * cv[n];
        #pragma unroll
        for (int off = 16; off > 0; off >>= 1) r += __shfl_xor_sync(0xffffffffu, r, off);
        if (lane == 0) red[n][wid] = r;
    }
    __syncthreads();
    const float gd = g_ff[d], bd = b_ff[d];
    #pragma unroll
    for (int n = 0; n < 8; n++) {
        float var = (red[n][0] + red[n][1]) * (1.f / 64.f);
        out[(i0 + n) * 64 + d] = fmaf(gd * cv[n], rsqrtf(var + 1e-5f), bd);
    }
}

extern "C" void kernel_launch(void* const* d_in, const int* in_sizes, int n_in,
                              void* d_out, int out_size)
{
    const float* coords = (const float*)d_in[0];
    const float* feats  = (const float*)d_in[1];
    const float* Wq  = (const float*)d_in[2];
    const float* bq  = (const float*)d_in[3];
    const float* Wk  = (const float*)d_in[4];
    const float* bk  = (const float*)d_in[5];
    const float* Wv  = (const float*)d_in[6];
    const float* bv  = (const float*)d_in[7];
    const float* Wl1 = (const float*)d_in[8];
    const float* bl1 = (const float*)d_in[9];
    const float* Wl2 = (const float*)d_in[10];
    const float* bl2 = (const float*)d_in[11];
    const float* Ww1 = (const float*)d_in[12];
    const float* bw1 = (const float*)d_in[13];
    const float* Ww2 = (const float*)d_in[14];
    const float* bw2 = (const float*)d_in[15];
    const float* g_att = (const float*)d_in[16];
    const float* b_att = (const float*)d_in[17];
    const float* Wsg = (const float*)d_in[18];
    const float* bsg = (const float*)d_in[19];
    const float* Wf  = (const float*)d_in[20];
    const float* bf  = (const float*)d_in[21];
    const float* g_ff = (const float*)d_in[22];
    const float* b_ff = (const float*)d_in[23];
    const int*   knn  = (const int*)d_in[24];

    cudaFuncSetAttribute(attn_kernel, cudaFuncAttributeMaxDynamicSharedMemorySize, SM_BYTES);

    prep_kernel<<<5, 256>>>(Wl2, Wk, Ww1, Ww2, Wv);
    attn_kernel<<<NN / 4, 128, SM_BYTES>>>(coords, feats, Wq, bq, bk, bv,
                                           Wl1, bl1, bl2, bw1, bw2,
                                           g_att, b_att, knn);
    gcn_kernel<<<NN / 8, 64>>>(coords, Wsg, bsg, Wf, bf, g_ff, b_ff, knn,
                               (float*)d_out);
}